// round 2
// baseline (speedup 1.0000x reference)
#include <cuda_runtime.h>
#include <math.h>

// ---------------- problem dims ----------------
#define B_   8
#define T_   16
#define N_   196
#define C_   768
#define H_   8
#define D_   96
#define MEM_ 196
#define HID_ 3072
#define ROWS_ (B_ * N_)          // 1568
#define SCALE_ 0.1020620726159657f  // 96^-0.5

// ---------------- scratch (device globals; no allocation) ----------------
__device__ float g_x   [B_*T_*N_*C_];   // LN'd input
__device__ float g_cat [ROWS_*2*C_];
__device__ float g_hid [ROWS_*HID_];
__device__ float g_cg  [ROWS_*C_];
__device__ float g_memh[ROWS_*C_];
__device__ float g_q   [ROWS_*C_];
__device__ float g_k   [ROWS_*C_];
__device__ float g_o   [B_*H_*N_*MEM_];
__device__ float g_c   [ROWS_*C_];
__device__ float g_c2  [ROWS_*C_];
__device__ float g_gate[B_*H_*MEM_];
__device__ float g_ap  [B_*C_];
__device__ float g_memA[ROWS_*C_];
__device__ float g_memB[ROWS_*C_];

__device__ __forceinline__ float gelu_exact(float x) {
    return 0.5f * x * (1.0f + erff(x * 0.70710678118654752f));
}

// ---------------- LayerNorm over C=768, one block per row ----------------
__global__ __launch_bounds__(256) void ln_kernel(
    const float* __restrict__ x, const float* __restrict__ w,
    const float* __restrict__ b, float* __restrict__ y)
{
    int row = blockIdx.x;
    const float* xr = x + (size_t)row * C_;
    float v[3], s = 0.f, s2 = 0.f;
#pragma unroll
    for (int i = 0; i < 3; i++) {
        v[i] = xr[threadIdx.x + i * 256];
        s += v[i]; s2 += v[i] * v[i];
    }
    __shared__ float red[18];
#pragma unroll
    for (int off = 16; off; off >>= 1) {
        s  += __shfl_down_sync(0xffffffffu, s, off);
        s2 += __shfl_down_sync(0xffffffffu, s2, off);
    }
    int wid = threadIdx.x >> 5, lane = threadIdx.x & 31;
    if (lane == 0) { red[wid] = s; red[8 + wid] = s2; }
    __syncthreads();
    if (threadIdx.x == 0) {
        float ts = 0.f, ts2 = 0.f;
        for (int i = 0; i < 8; i++) { ts += red[i]; ts2 += red[8 + i]; }
        red[16] = ts; red[17] = ts2;
    }
    __syncthreads();
    float mean = red[16] * (1.0f / C_);
    float var  = red[17] * (1.0f / C_) - mean * mean;
    float inv  = rsqrtf(var + 1e-5f);
    float* yr = y + (size_t)row * C_;
#pragma unroll
    for (int i = 0; i < 3; i++) {
        int c = threadIdx.x + i * 256;
        yr[c] = (v[i] - mean) * inv * w[c] + b[c];
    }
}

// ---------------- final: LN(c2 + gate*memh) ----------------
__global__ __launch_bounds__(256) void final_kernel(
    const float* __restrict__ c2, const float* __restrict__ gate,
    const float* __restrict__ memh, const float* __restrict__ w,
    const float* __restrict__ bb, float* __restrict__ y)
{
    int row = blockIdx.x;              // b*MEM + m
    int b = row / MEM_, m = row % MEM_;
    float v[3], s = 0.f, s2 = 0.f;
#pragma unroll
    for (int i = 0; i < 3; i++) {
        int c = threadIdx.x + i * 256;
        float g = gate[(b * H_ + (c / D_)) * MEM_ + m];
        v[i] = c2[(size_t)row * C_ + c] + g * memh[(size_t)row * C_ + c];
        s += v[i]; s2 += v[i] * v[i];
    }
    __shared__ float red[18];
#pragma unroll
    for (int off = 16; off; off >>= 1) {
        s  += __shfl_down_sync(0xffffffffu, s, off);
        s2 += __shfl_down_sync(0xffffffffu, s2, off);
    }
    int wid = threadIdx.x >> 5, lane = threadIdx.x & 31;
    if (lane == 0) { red[wid] = s; red[8 + wid] = s2; }
    __syncthreads();
    if (threadIdx.x == 0) {
        float ts = 0.f, ts2 = 0.f;
        for (int i = 0; i < 8; i++) { ts += red[i]; ts2 += red[8 + i]; }
        red[16] = ts; red[17] = ts2;
    }
    __syncthreads();
    float mean = red[16] * (1.0f / C_);
    float var  = red[17] * (1.0f / C_) - mean * mean;
    float inv  = rsqrtf(var + 1e-5f);
    float* yr = y + (size_t)row * C_;
#pragma unroll
    for (int i = 0; i < 3; i++) {
        int c = threadIdx.x + i * 256;
        yr[c] = (v[i] - mean) * inv * w[c] + bb[c];
    }
}

// ---------------- mem init: copy frame 0 of LN'd x ----------------
__global__ void initmem_kernel(const float* __restrict__ x, float* __restrict__ mem)
{
    int idx = blockIdx.x * 256 + threadIdx.x;
    if (idx >= B_ * MEM_ * C_) return;
    int b = idx / (MEM_ * C_);
    int r = idx % (MEM_ * C_);
    mem[idx] = x[(size_t)b * T_ * N_ * C_ + r];
}

// ---------------- ap = mean over MEM ----------------
__global__ void ap_kernel(const float* __restrict__ mem, float* __restrict__ ap)
{
    int idx = blockIdx.x * 256 + threadIdx.x;  // b*C + c
    if (idx >= B_ * C_) return;
    int b = idx / C_, c = idx % C_;
    float s = 0.f;
    const float* p = mem + (size_t)b * MEM_ * C_ + c;
    for (int m = 0; m < MEM_; m++) s += p[(size_t)m * C_];
    ap[idx] = s * (1.0f / MEM_);
}

// ---------------- cat = [fea(t), broadcast(ap)] ----------------
__global__ void cat_kernel(const float* __restrict__ x, const float* __restrict__ ap,
                           float* __restrict__ cat, int t)
{
    int idx = blockIdx.x * 256 + threadIdx.x;
    if (idx >= ROWS_ * 2 * C_) return;
    int row = idx / (2 * C_), j = idx % (2 * C_);
    int b = row / N_, n = row % N_;
    cat[idx] = (j < C_) ? x[(((size_t)b * T_ + t) * N_ + n) * C_ + j]
                        : ap[b * C_ + (j - C_)];
}

// ---------------- SGEMM 128x128 tile, 8x8 per thread ----------------
__global__ __launch_bounds__(256) void sgemm128(
    const float* __restrict__ A, const float* __restrict__ W,
    const float* __restrict__ bias, float* __restrict__ out,
    int M, int N, int K, int act)
{
    __shared__ float As[16][128];
    __shared__ float Bs[16][128];
    int bm = blockIdx.y * 128, bn = blockIdx.x * 128;
    int tid = threadIdx.x;
    int tx = tid & 15, ty = tid >> 4;
    float acc[8][8];
#pragma unroll
    for (int i = 0; i < 8; i++)
#pragma unroll
        for (int j = 0; j < 8; j++) acc[i][j] = 0.f;
    int aRow = tid >> 2, aCol = (tid & 3) * 4;
    int bRow = tid >> 5, bCol = (tid & 31) * 4;

    for (int k0 = 0; k0 < K; k0 += 16) {
#pragma unroll
        for (int i = 0; i < 2; i++) {
            int r = aRow + i * 64, gr = bm + r;
            float4 v = make_float4(0.f, 0.f, 0.f, 0.f);
            if (gr < M) v = *(const float4*)(A + (size_t)gr * K + k0 + aCol);
            As[aCol + 0][r] = v.x; As[aCol + 1][r] = v.y;
            As[aCol + 2][r] = v.z; As[aCol + 3][r] = v.w;
        }
#pragma unroll
        for (int i = 0; i < 2; i++) {
            int r = bRow + i * 8;
            *(float4*)(&Bs[r][bCol]) = *(const float4*)(W + (size_t)(k0 + r) * N + bn + bCol);
        }
        __syncthreads();
#pragma unroll
        for (int kk = 0; kk < 16; kk++) {
            float a[8], bv[8];
#pragma unroll
            for (int i = 0; i < 8; i++) a[i] = As[kk][ty * 8 + i];
#pragma unroll
            for (int j = 0; j < 8; j++) bv[j] = Bs[kk][tx * 8 + j];
#pragma unroll
            for (int i = 0; i < 8; i++)
#pragma unroll
                for (int j = 0; j < 8; j++) acc[i][j] = fmaf(a[i], bv[j], acc[i][j]);
        }
        __syncthreads();
    }
#pragma unroll
    for (int i = 0; i < 8; i++) {
        int gr = bm + ty * 8 + i;
        if (gr >= M) continue;
#pragma unroll
        for (int j = 0; j < 8; j++) {
            int gc = bn + tx * 8 + j;
            float v = acc[i][j] + bias[gc];
            if (act) v = gelu_exact(v);
            out[(size_t)gr * N + gc] = v;
        }
    }
}

// ---------------- SGEMM 64x64 tile, 4x4 per thread (small N) ----------------
__global__ __launch_bounds__(256) void sgemm64(
    const float* __restrict__ A, const float* __restrict__ W,
    const float* __restrict__ bias, float* __restrict__ out,
    int M, int N, int K, int act)
{
    __shared__ float As[16][64];
    __shared__ float Bs[16][64];
    int bm = blockIdx.y * 64, bn = blockIdx.x * 64;
    int tid = threadIdx.x;
    int tx = tid & 15, ty = tid >> 4;
    float acc[4][4];
#pragma unroll
    for (int i = 0; i < 4; i++)
#pragma unroll
        for (int j = 0; j < 4; j++) acc[i][j] = 0.f;
    int aRow = tid >> 2, aCol = (tid & 3) * 4;
    int bRow = tid >> 4, bCol = (tid & 15) * 4;

    for (int k0 = 0; k0 < K; k0 += 16) {
        {
            int gr = bm + aRow;
            float4 v = make_float4(0.f, 0.f, 0.f, 0.f);
            if (gr < M) v = *(const float4*)(A + (size_t)gr * K + k0 + aCol);
            As[aCol + 0][aRow] = v.x; As[aCol + 1][aRow] = v.y;
            As[aCol + 2][aRow] = v.z; As[aCol + 3][aRow] = v.w;
        }
        *(float4*)(&Bs[bRow][bCol]) = *(const float4*)(W + (size_t)(k0 + bRow) * N + bn + bCol);
        __syncthreads();
#pragma unroll
        for (int kk = 0; kk < 16; kk++) {
            float a[4], bv[4];
#pragma unroll
            for (int i = 0; i < 4; i++) a[i] = As[kk][ty * 4 + i];
#pragma unroll
            for (int j = 0; j < 4; j++) bv[j] = Bs[kk][tx * 4 + j];
#pragma unroll
            for (int i = 0; i < 4; i++)
#pragma unroll
                for (int j = 0; j < 4; j++) acc[i][j] = fmaf(a[i], bv[j], acc[i][j]);
        }
        __syncthreads();
    }
#pragma unroll
    for (int i = 0; i < 4; i++) {
        int gr = bm + ty * 4 + i;
        if (gr >= M) continue;
#pragma unroll
        for (int j = 0; j < 4; j++) {
            int gc = bn + tx * 4 + j;
            float v = acc[i][j] + bias[gc];
            if (act) v = gelu_exact(v);
            out[(size_t)gr * N + gc] = v;
        }
    }
}

// ---------------- attention: o = sigmoid(scale * q.k) per (b,h) ----------------
__global__ __launch_bounds__(256) void attn_kernel(
    const float* __restrict__ q, const float* __restrict__ k, float* __restrict__ o)
{
    int bh = blockIdx.z, b = bh >> 3, h = bh & 7;
    int m0 = blockIdx.x * 32, n0 = blockIdx.y * 32;
    __shared__ float Qs[32][97];
    __shared__ float Ks[32][97];
    for (int idx = threadIdx.x; idx < 32 * 96; idx += 256) {
        int r = idx / 96, d = idx % 96;
        int n = n0 + r;
        Qs[r][d] = (n < N_) ? q[((size_t)b * N_ + n) * C_ + h * D_ + d] : 0.f;
        int m = m0 + r;
        Ks[r][d] = (m < MEM_) ? k[((size_t)b * MEM_ + m) * C_ + h * D_ + d] : 0.f;
    }
    __syncthreads();
    int nl = threadIdx.x & 31, mg = threadIdx.x >> 5;
    float acc[4] = {0.f, 0.f, 0.f, 0.f};
    for (int d = 0; d < 96; d++) {
        float qv = Qs[nl][d];
#pragma unroll
        for (int i = 0; i < 4; i++) acc[i] = fmaf(qv, Ks[mg * 4 + i][d], acc[i]);
    }
    int n = n0 + nl;
    if (n < N_) {
#pragma unroll
        for (int i = 0; i < 4; i++) {
            int m = m0 + mg * 4 + i;
            if (m < MEM_) {
                float v = acc[i] * SCALE_;
                o[(((size_t)b * H_ + h) * N_ + n) * MEM_ + m] = 1.0f / (1.0f + expf(-v));
            }
        }
    }
}

// ---------------- gate[b,h,m] = 1 - mean_n o ----------------
__global__ void gate_kernel(const float* __restrict__ o, float* __restrict__ gate)
{
    int idx = blockIdx.x * 256 + threadIdx.x;   // bh*MEM + m
    if (idx >= B_ * H_ * MEM_) return;
    int m = idx % MEM_, bh = idx / MEM_;
    const float* op = o + (size_t)bh * N_ * MEM_ + m;
    float s = 0.f;
    for (int n = 0; n < N_; n++) s += op[(size_t)n * MEM_];
    gate[idx] = 1.0f - s * (1.0f / N_);
}

// ---------------- c[b,m,hD+d] = sum_n o[b,h,n,m]*cg[b,n,hD+d] ----------------
__global__ __launch_bounds__(256) void cgather_kernel(
    const float* __restrict__ o, const float* __restrict__ cg, float* __restrict__ c)
{
    int bh = blockIdx.y, b = bh >> 3, h = bh & 7;
    int m0 = blockIdx.x * 32;
    int ml = threadIdx.x & 31, dg = threadIdx.x >> 5;   // d = dg*12 .. +11
    __shared__ float Os[32][33];
    __shared__ float Gs[32][97];
    float acc[12];
#pragma unroll
    for (int j = 0; j < 12; j++) acc[j] = 0.f;

    for (int n0 = 0; n0 < N_; n0 += 32) {
        for (int idx = threadIdx.x; idx < 32 * 32; idx += 256) {
            int r = idx >> 5, cc = idx & 31;
            int n = n0 + r, m = m0 + cc;
            Os[r][cc] = (n < N_ && m < MEM_)
                          ? o[(((size_t)b * H_ + h) * N_ + n) * MEM_ + m] : 0.f;
        }
        for (int idx = threadIdx.x; idx < 32 * 96; idx += 256) {
            int r = idx / 96, d = idx % 96;
            int n = n0 + r;
            Gs[r][d] = (n < N_) ? cg[((size_t)b * N_ + n) * C_ + h * D_ + d] : 0.f;
        }
        __syncthreads();
#pragma unroll 8
        for (int nn = 0; nn < 32; nn++) {
            float ov = Os[nn][ml];
#pragma unroll
            for (int j = 0; j < 12; j++) acc[j] = fmaf(ov, Gs[nn][dg * 12 + j], acc[j]);
        }
        __syncthreads();
    }
    int m = m0 + ml;
    if (m < MEM_) {
#pragma unroll
        for (int j = 0; j < 12; j++)
            c[((size_t)b * MEM_ + m) * C_ + h * D_ + dg * 12 + j] = acc[j];
    }
}

// ---------------- host orchestration ----------------
static void launch_gemm(const float* A, const float* W, const float* bias, float* out,
                        int M, int N, int K, int act)
{
    if (N >= 1536) {
        dim3 g(N / 128, (M + 127) / 128);
        sgemm128<<<g, 256>>>(A, W, bias, out, M, N, K, act);
    } else {
        dim3 g(N / 64, (M + 63) / 64);
        sgemm64<<<g, 256>>>(A, W, bias, out, M, N, K, act);
    }
}

extern "C" void kernel_launch(void* const* d_in, const int* in_sizes, int n_in,
                              void* d_out, int out_size)
{
    const float* cur_fea = (const float*)d_in[0];
    const float* n1w = (const float*)d_in[1];
    const float* n1b = (const float*)d_in[2];
    const float* n2w = (const float*)d_in[3];
    const float* n2b = (const float*)d_in[4];
    const float* c_w1 = (const float*)d_in[5];
    const float* c_b1 = (const float*)d_in[6];
    const float* c_w2 = (const float*)d_in[7];
    const float* c_b2 = (const float*)d_in[8];
    const float* m_w1 = (const float*)d_in[9];
    const float* m_b1 = (const float*)d_in[10];
    const float* m_w2 = (const float*)d_in[11];
    const float* m_b2 = (const float*)d_in[12];
    const float* p_w1 = (const float*)d_in[13];
    const float* p_b1 = (const float*)d_in[14];
    const float* p_w2 = (const float*)d_in[15];
    const float* p_b2 = (const float*)d_in[16];
    const float* q_w = (const float*)d_in[17];
    const float* q_b = (const float*)d_in[18];
    const float* k_w = (const float*)d_in[19];
    const float* k_b = (const float*)d_in[20];

    float *x, *cat, *hid, *cg, *memh, *q, *k, *o, *c, *c2, *gate, *ap, *memA, *memB;
    cudaGetSymbolAddress((void**)&x,    g_x);
    cudaGetSymbolAddress((void**)&cat,  g_cat);
    cudaGetSymbolAddress((void**)&hid,  g_hid);
    cudaGetSymbolAddress((void**)&cg,   g_cg);
    cudaGetSymbolAddress((void**)&memh, g_memh);
    cudaGetSymbolAddress((void**)&q,    g_q);
    cudaGetSymbolAddress((void**)&k,    g_k);
    cudaGetSymbolAddress((void**)&o,    g_o);
    cudaGetSymbolAddress((void**)&c,    g_c);
    cudaGetSymbolAddress((void**)&c2,   g_c2);
    cudaGetSymbolAddress((void**)&gate, g_gate);
    cudaGetSymbolAddress((void**)&ap,   g_ap);
    cudaGetSymbolAddress((void**)&memA, g_memA);
    cudaGetSymbolAddress((void**)&memB, g_memB);

    // LN over full input
    ln_kernel<<<B_ * T_ * N_, 256>>>(cur_fea, n1w, n1b, x);
    // init memory = frame 0
    initmem_kernel<<<(B_ * MEM_ * C_ + 255) / 256, 256>>>(x, memA);

    float* mcur = memA;
    float* mnxt = memB;

    for (int t = 1; t < T_; t++) {
        ap_kernel<<<(B_ * C_ + 255) / 256, 256>>>(mcur, ap);
        cat_kernel<<<(ROWS_ * 2 * C_ + 255) / 256, 256>>>(x, ap, cat, t);

        launch_gemm(cat,  c_w1, c_b1, hid,  ROWS_, HID_, 2 * C_, 1);  // fc1_c + gelu
        launch_gemm(hid,  c_w2, c_b2, cg,   ROWS_, C_,   HID_,   0);  // fc2_c
        launch_gemm(mcur, m_w1, m_b1, hid,  ROWS_, HID_, C_,     1);  // fc1_m + gelu
        launch_gemm(hid,  m_w2, m_b2, memh, ROWS_, C_,   HID_,   0);  // fc2_m
        launch_gemm(cg,   q_w,  q_b,  q,    ROWS_, C_,   C_,     0);  // q proj
        launch_gemm(mcur, k_w,  k_b,  k,    ROWS_, C_,   C_,     0);  // k proj

        attn_kernel<<<dim3(7, 7, B_ * H_), 256>>>(q, k, o);
        gate_kernel<<<(B_ * H_ * MEM_ + 255) / 256, 256>>>(o, gate);
        cgather_kernel<<<dim3(7, B_ * H_), 256>>>(o, cg, c);

        launch_gemm(c,   p_w1, p_b1, hid, ROWS_, HID_, C_,   1);      // fc1_p + gelu
        launch_gemm(hid, p_w2, p_b2, c2,  ROWS_, C_,   HID_, 0);      // fc2_p

        float* dst = (t == T_ - 1) ? (float*)d_out : mnxt;
        final_kernel<<<B_ * MEM_, 256>>>(c2, gate, memh, n2w, n2b, dst);

        float* tmp = mcur; mcur = mnxt; mnxt = tmp;
    }
}

// round 4
// speedup vs baseline: 1.7040x; 1.7040x over previous
#include <cuda_runtime.h>
#include <cuda_bf16.h>
#include <math.h>
#include <stdint.h>

#define B_   8
#define T_   16
#define N_   196
#define C_   768
#define H_   8
#define D_   96
#define MEM_ 196
#define HID_ 3072
#define ROWS_ 1568
#define SCALE_ 0.1020620726159657f

typedef __nv_bfloat16 bf16;

// ---------------- fp32 scratch ----------------
__device__ __align__(256) float g_x   [B_*T_*N_*C_];
__device__ __align__(256) float g_cat [ROWS_*2*C_];
__device__ __align__(256) float g_hid [ROWS_*HID_];
__device__ __align__(256) float g_cg  [ROWS_*C_];
__device__ __align__(256) float g_memh[ROWS_*C_];
__device__ __align__(256) float g_q   [ROWS_*C_];
__device__ __align__(256) float g_kk  [ROWS_*C_];
__device__ __align__(256) float g_o   [B_*H_*N_*MEM_];
__device__ __align__(256) float g_c   [ROWS_*C_];
__device__ __align__(256) float g_c2  [ROWS_*C_];
__device__ __align__(256) float g_gate[B_*H_*MEM_];
__device__ __align__(256) float g_ap  [B_*C_];
__device__ __align__(256) float g_memA[ROWS_*C_];
__device__ __align__(256) float g_memB[ROWS_*C_];

// ---------------- augmented bf16 buffers: [rows][3K] = [hi | hi | lo] ----------------
__device__ __align__(256) uint16_t g_aBig[ROWS_*3*HID_];   // cat(4608) / hid(9216)
__device__ __align__(256) uint16_t g_aSm [ROWS_*3*C_];     // mem / cg / c (2304)

// weights augmented [N][3K] = [hi | lo | hi]
__device__ __align__(256) uint16_t g_wc1[HID_*3*2*C_];
__device__ __align__(256) uint16_t g_wc2[C_*3*HID_];
__device__ __align__(256) uint16_t g_wm1[HID_*3*C_];
__device__ __align__(256) uint16_t g_wm2[C_*3*HID_];
__device__ __align__(256) uint16_t g_wp1[HID_*3*C_];
__device__ __align__(256) uint16_t g_wp2[C_*3*HID_];
__device__ __align__(256) uint16_t g_wq [C_*3*C_];
__device__ __align__(256) uint16_t g_wk [C_*3*C_];

__device__ __forceinline__ float gelu_exact(float x) {
    return 0.5f * x * (1.0f + erff(x * 0.70710678118654752f));
}
__device__ __forceinline__ uint32_t smem_u32(const void* p) {
    uint32_t a;
    asm("{ .reg .u64 t; cvta.to.shared.u64 t, %1; cvt.u32.u64 %0, t; }" : "=r"(a) : "l"(p));
    return a;
}
__device__ __forceinline__ void cp16(uint32_t dst, const void* src, int pred) {
    int sz = pred ? 16 : 0;
    asm volatile("cp.async.cg.shared.global [%0], [%1], 16, %2;" :: "r"(dst), "l"(src), "r"(sz) : "memory");
}
__device__ __forceinline__ uint32_t swz(uint32_t o) { return o ^ ((o >> 3) & 0x70); }

#define LDSM4(r0, r1, r2, r3, addr) \
    asm volatile("ldmatrix.sync.aligned.m8n8.x4.shared.b16 {%0,%1,%2,%3}, [%4];" \
        : "=r"(r0), "=r"(r1), "=r"(r2), "=r"(r3) : "r"(addr))

#define MMA16816(d, a, b0, b1) \
    asm volatile("mma.sync.aligned.m16n8k16.row.col.f32.bf16.bf16.f32 " \
        "{%0,%1,%2,%3}, {%4,%5,%6,%7}, {%8,%9}, {%0,%1,%2,%3};" \
        : "+f"((d)[0]), "+f"((d)[1]), "+f"((d)[2]), "+f"((d)[3]) \
        : "r"((a)[0]), "r"((a)[1]), "r"((a)[2]), "r"((a)[3]), "r"(b0), "r"(b1))

// ==================== bf16 mma.sync GEMM: out[M,N] = A'[M,K3] * W'^T[N,K3] ====================
#define GS 3

template<int BM>
__global__ __launch_bounds__(256, 1) void gemm_mma(
    const bf16* __restrict__ A, const bf16* __restrict__ Bw,
    const float* __restrict__ bias, float* __restrict__ out,
    int M, int N, int K3, int act)
{
    constexpr int MT = BM / 32;              // m16 tiles per warp
    constexpr int A_BYTES = BM * 128;        // A stage bytes (BM rows x 64 bf16)
    constexpr int STG = A_BYTES + 16384;     // + B stage (128 rows x 64 bf16)
    extern __shared__ __align__(1024) char smem[];
    uint32_t sb = smem_u32(smem);
    int tid = threadIdx.x, wid = tid >> 5, lane = tid & 31;
    int bm = blockIdx.y * BM, bn = blockIdx.x * 128;
    int m0w = (wid & 1) * (BM / 2);
    int n0w = (wid >> 1) * 32;
    int NC = K3 >> 6;

    auto load_stage = [&](int c) {
        uint32_t stage = sb + (c % GS) * STG;
        int k0 = c << 6;
        constexpr int TOT = BM * 8 + 1024;
        for (int g = tid; g < TOT; g += 256) {
            int isB = (g >= BM * 8);
            int q = isB ? (g - BM * 8) : g;
            int row = q >> 3, c16 = q & 7;
            uint32_t dst = stage + (isB ? A_BYTES : 0) + swz((row << 7) + (c16 << 4));
            const bf16* src;
            int pred = 1;
            if (!isB) {
                int gr = bm + row; pred = gr < M;
                src = A + (size_t)(pred ? gr : 0) * K3 + k0 + (c16 << 3);
            } else {
                int gr = bn + row;
                src = Bw + (size_t)gr * K3 + k0 + (c16 << 3);
            }
            cp16(dst, src, pred);
        }
        asm volatile("cp.async.commit_group;" ::: "memory");
    };

    float acc[MT][4][4];
#pragma unroll
    for (int mt = 0; mt < MT; mt++)
#pragma unroll
        for (int nt = 0; nt < 4; nt++)
#pragma unroll
            for (int i = 0; i < 4; i++) acc[mt][nt][i] = 0.f;

    load_stage(0);
    load_stage(1);

    for (int c = 0; c < NC; c++) {
        if (c == NC - 1) asm volatile("cp.async.wait_group 0;" ::: "memory");
        else             asm volatile("cp.async.wait_group 1;" ::: "memory");
        __syncthreads();
        if (c + 2 < NC) load_stage(c + 2);

        uint32_t sA = sb + (c % GS) * STG;
        uint32_t sB = sA + A_BYTES;
#pragma unroll
        for (int ks = 0; ks < 4; ks++) {
            uint32_t a[MT][4], bfr[2][4];
#pragma unroll
            for (int mt = 0; mt < MT; mt++) {
                int row = m0w + mt * 16 + (lane & 15);
                int ch = ks * 2 + (lane >> 4);
                uint32_t ad = sA + swz((uint32_t)(row << 7) + (ch << 4));
                LDSM4(a[mt][0], a[mt][1], a[mt][2], a[mt][3], ad);
            }
#pragma unroll
            for (int bp = 0; bp < 2; bp++) {
                int row = n0w + bp * 16 + (lane & 7) + ((lane & 16) >> 1);
                int ch = ks * 2 + ((lane & 8) >> 3);
                uint32_t ad = sB + swz((uint32_t)(row << 7) + (ch << 4));
                LDSM4(bfr[bp][0], bfr[bp][1], bfr[bp][2], bfr[bp][3], ad);
            }
#pragma unroll
            for (int mt = 0; mt < MT; mt++)
#pragma unroll
                for (int nt = 0; nt < 4; nt++)
                    MMA16816(acc[mt][nt], a[mt],
                             bfr[nt >> 1][(nt & 1) * 2], bfr[nt >> 1][(nt & 1) * 2 + 1]);
        }
    }

    // epilogue: registers -> global, bias + optional gelu
#pragma unroll
    for (int mt = 0; mt < MT; mt++) {
        int r0 = bm + m0w + mt * 16 + (lane >> 2);
        int r1 = r0 + 8;
#pragma unroll
        for (int nt = 0; nt < 4; nt++) {
            int col = bn + n0w + nt * 8 + ((lane & 3) << 1);
            float bv0 = bias[col], bv1 = bias[col + 1];
            if (r0 < M) {
                float v0 = acc[mt][nt][0] + bv0, v1 = acc[mt][nt][1] + bv1;
                if (act) { v0 = gelu_exact(v0); v1 = gelu_exact(v1); }
                *(float2*)(out + (size_t)r0 * N + col) = make_float2(v0, v1);
            }
            if (r1 < M) {
                float v2 = acc[mt][nt][2] + bv0, v3 = acc[mt][nt][3] + bv1;
                if (act) { v2 = gelu_exact(v2); v3 = gelu_exact(v3); }
                *(float2*)(out + (size_t)r1 * N + col) = make_float2(v2, v3);
            }
        }
    }
}

// ==================== conversion: fp32 [rows][K] -> aug bf16 [rows][3K] = [hi|hi|lo] ====================
__global__ void cvt_split(const float* __restrict__ x, uint16_t* __restrict__ aug,
                          int rows, int K)
{
    int K4 = K >> 2;
    int idx = blockIdx.x * 256 + threadIdx.x;
    if (idx >= rows * K4) return;
    int r = idx / K4, j = (idx % K4) << 2;
    float4 v = *(const float4*)(x + (size_t)r * K + j);
    bf16 h0 = __float2bfloat16(v.x), h1 = __float2bfloat16(v.y);
    bf16 h2 = __float2bfloat16(v.z), h3 = __float2bfloat16(v.w);
    __nv_bfloat162 hh[2], ll[2];
    hh[0] = __halves2bfloat162(h0, h1);
    hh[1] = __halves2bfloat162(h2, h3);
    ll[0] = __halves2bfloat162(__float2bfloat16(v.x - __bfloat162float(h0)),
                               __float2bfloat16(v.y - __bfloat162float(h1)));
    ll[1] = __halves2bfloat162(__float2bfloat16(v.z - __bfloat162float(h2)),
                               __float2bfloat16(v.w - __bfloat162float(h3)));
    size_t base = (size_t)r * 3 * K;
    *(uint2*)(aug + base + j)         = *(uint2*)hh;
    *(uint2*)(aug + base + K + j)     = *(uint2*)hh;
    *(uint2*)(aug + base + 2 * K + j) = *(uint2*)ll;
}

// W [K][N] fp32 -> aug bf16 [N][3K] = [hi|lo|hi]
__global__ void wsplitT(const float* __restrict__ w, uint16_t* __restrict__ aug,
                        int K, int N)
{
    __shared__ float t[32][33];
    int n0 = blockIdx.x * 32, k0 = blockIdx.y * 32;
    int tx = threadIdx.x, ty = threadIdx.y;
#pragma unroll
    for (int j = 0; j < 4; j++)
        t[ty + 8 * j][tx] = w[(size_t)(k0 + ty + 8 * j) * N + n0 + tx];
    __syncthreads();
#pragma unroll
    for (int j = 0; j < 4; j++) {
        float v = t[tx][ty + 8 * j];
        int n = n0 + ty + 8 * j, k = k0 + tx;
        bf16 h = __float2bfloat16(v);
        bf16 l = __float2bfloat16(v - __bfloat162float(h));
        size_t base = (size_t)n * 3 * K;
        *(bf16*)(aug + base + k)         = h;
        *(bf16*)(aug + base + K + k)     = l;   // pairs with A's 2nd hi slot
        *(bf16*)(aug + base + 2 * K + k) = h;   // pairs with A's lo slot
    }
}

// ==================== elementwise / attention (fp32, proven) ====================
__global__ __launch_bounds__(256) void ln_kernel(
    const float* __restrict__ x, const float* __restrict__ w,
    const float* __restrict__ b, float* __restrict__ y)
{
    int row = blockIdx.x;
    const float* xr = x + (size_t)row * C_;
    float v[3], s = 0.f, s2 = 0.f;
#pragma unroll
    for (int i = 0; i < 3; i++) { v[i] = xr[threadIdx.x + i*256]; s += v[i]; s2 += v[i]*v[i]; }
    __shared__ float red[18];
#pragma unroll
    for (int off = 16; off; off >>= 1) {
        s  += __shfl_down_sync(0xffffffffu, s, off);
        s2 += __shfl_down_sync(0xffffffffu, s2, off);
    }
    int wid = threadIdx.x >> 5, lane = threadIdx.x & 31;
    if (lane == 0) { red[wid] = s; red[8+wid] = s2; }
    __syncthreads();
    if (threadIdx.x == 0) {
        float ts = 0.f, ts2 = 0.f;
        for (int i = 0; i < 8; i++) { ts += red[i]; ts2 += red[8+i]; }
        red[16] = ts; red[17] = ts2;
    }
    __syncthreads();
    float mean = red[16] * (1.0f/C_);
    float inv  = rsqrtf(red[17] * (1.0f/C_) - mean*mean + 1e-5f);
    float* yr = y + (size_t)row * C_;
#pragma unroll
    for (int i = 0; i < 3; i++) {
        int c = threadIdx.x + i*256;
        yr[c] = (v[i] - mean) * inv * w[c] + b[c];
    }
}

__global__ __launch_bounds__(256) void final_kernel(
    const float* __restrict__ c2, const float* __restrict__ gate,
    const float* __restrict__ memh, const float* __restrict__ w,
    const float* __restrict__ bb, float* __restrict__ y)
{
    int row = blockIdx.x;
    int b = row / MEM_, m = row % MEM_;
    float v[3], s = 0.f, s2 = 0.f;
#pragma unroll
    for (int i = 0; i < 3; i++) {
        int c = threadIdx.x + i*256;
        float g = gate[(b*H_ + (c/D_))*MEM_ + m];
        v[i] = c2[(size_t)row*C_ + c] + g * memh[(size_t)row*C_ + c];
        s += v[i]; s2 += v[i]*v[i];
    }
    __shared__ float red[18];
#pragma unroll
    for (int off = 16; off; off >>= 1) {
        s  += __shfl_down_sync(0xffffffffu, s, off);
        s2 += __shfl_down_sync(0xffffffffu, s2, off);
    }
    int wid = threadIdx.x >> 5, lane = threadIdx.x & 31;
    if (lane == 0) { red[wid] = s; red[8+wid] = s2; }
    __syncthreads();
    if (threadIdx.x == 0) {
        float ts = 0.f, ts2 = 0.f;
        for (int i = 0; i < 8; i++) { ts += red[i]; ts2 += red[8+i]; }
        red[16] = ts; red[17] = ts2;
    }
    __syncthreads();
    float mean = red[16] * (1.0f/C_);
    float inv  = rsqrtf(red[17] * (1.0f/C_) - mean*mean + 1e-5f);
    float* yr = y + (size_t)row * C_;
#pragma unroll
    for (int i = 0; i < 3; i++) {
        int c = threadIdx.x + i*256;
        yr[c] = (v[i] - mean) * inv * w[c] + bb[c];
    }
}

__global__ void initmem_kernel(const float* __restrict__ x, float* __restrict__ mem)
{
    int idx = blockIdx.x * 256 + threadIdx.x;
    if (idx >= B_*MEM_*C_) return;
    int b = idx / (MEM_*C_), r = idx % (MEM_*C_);
    mem[idx] = x[(size_t)b*T_*N_*C_ + r];
}

__global__ void ap_kernel(const float* __restrict__ mem, float* __restrict__ ap)
{
    int idx = blockIdx.x * 256 + threadIdx.x;
    if (idx >= B_*C_) return;
    int b = idx / C_, c = idx % C_;
    float s = 0.f;
    const float* p = mem + (size_t)b*MEM_*C_ + c;
    for (int m = 0; m < MEM_; m++) s += p[(size_t)m*C_];
    ap[idx] = s * (1.0f/MEM_);
}

__global__ void cat_kernel(const float* __restrict__ x, const float* __restrict__ ap,
                           float* __restrict__ cat, int t)
{
    int idx = blockIdx.x * 256 + threadIdx.x;
    if (idx >= ROWS_*2*C_) return;
    int row = idx / (2*C_), j = idx % (2*C_);
    int b = row / N_, n = row % N_;
    cat[idx] = (j < C_) ? x[(((size_t)b*T_ + t)*N_ + n)*C_ + j] : ap[b*C_ + (j - C_)];
}

__global__ __launch_bounds__(256) void attn_kernel(
    const float* __restrict__ q, const float* __restrict__ k, float* __restrict__ o)
{
    int bh = blockIdx.z, b = bh >> 3, h = bh & 7;
    int m0 = blockIdx.x * 32, n0 = blockIdx.y * 32;
    __shared__ float Qs[32][97];
    __shared__ float Ks[32][97];
    for (int idx = threadIdx.x; idx < 32*96; idx += 256) {
        int r = idx / 96, d = idx % 96;
        int n = n0 + r;
        Qs[r][d] = (n < N_) ? q[((size_t)b*N_ + n)*C_ + h*D_ + d] : 0.f;
        int m = m0 + r;
        Ks[r][d] = (m < MEM_) ? k[((size_t)b*MEM_ + m)*C_ + h*D_ + d] : 0.f;
    }
    __syncthreads();
    int nl = threadIdx.x & 31, mg = threadIdx.x >> 5;
    float acc[4] = {0.f, 0.f, 0.f, 0.f};
    for (int d = 0; d < 96; d++) {
        float qv = Qs[nl][d];
#pragma unroll
        for (int i = 0; i < 4; i++) acc[i] = fmaf(qv, Ks[mg*4 + i][d], acc[i]);
    }
    int n = n0 + nl;
    if (n < N_) {
#pragma unroll
        for (int i = 0; i < 4; i++) {
            int m = m0 + mg*4 + i;
            if (m < MEM_)
                o[(((size_t)b*H_ + h)*N_ + n)*MEM_ + m] = 1.0f / (1.0f + expf(-acc[i]*SCALE_));
        }
    }
}

__global__ void gate_kernel(const float* __restrict__ o, float* __restrict__ gate)
{
    int idx = blockIdx.x * 256 + threadIdx.x;
    if (idx >= B_*H_*MEM_) return;
    int m = idx % MEM_, bh = idx / MEM_;
    const float* op = o + (size_t)bh*N_*MEM_ + m;
    float s = 0.f;
    for (int n = 0; n < N_; n++) s += op[(size_t)n*MEM_];
    gate[idx] = 1.0f - s * (1.0f/N_);
}

__global__ __launch_bounds__(256) void cgather_kernel(
    const float* __restrict__ o, const float* __restrict__ cg, float* __restrict__ c)
{
    int bh = blockIdx.y, b = bh >> 3, h = bh & 7;
    int m0 = blockIdx.x * 32;
    int ml = threadIdx.x & 31, dg = threadIdx.x >> 5;
    __shared__ float Os[32][33];
    __shared__ float Gs[32][97];
    float acc[12];
#pragma unroll
    for (int j = 0; j < 12; j++) acc[j] = 0.f;
    for (int n0 = 0; n0 < N_; n0 += 32) {
        for (int idx = threadIdx.x; idx < 32*32; idx += 256) {
            int r = idx >> 5, cc = idx & 31;
            int n = n0 + r, m = m0 + cc;
            Os[r][cc] = (n < N_ && m < MEM_) ? o[(((size_t)b*H_ + h)*N_ + n)*MEM_ + m] : 0.f;
        }
        for (int idx = threadIdx.x; idx < 32*96; idx += 256) {
            int r = idx / 96, d = idx % 96;
            int n = n0 + r;
            Gs[r][d] = (n < N_) ? cg[((size_t)b*N_ + n)*C_ + h*D_ + d] : 0.f;
        }
        __syncthreads();
#pragma unroll 8
        for (int nn = 0; nn < 32; nn++) {
            float ov = Os[nn][ml];
#pragma unroll
            for (int j = 0; j < 12; j++) acc[j] = fmaf(ov, Gs[nn][dg*12 + j], acc[j]);
        }
        __syncthreads();
    }
    int m = m0 + ml;
    if (m < MEM_) {
#pragma unroll
        for (int j = 0; j < 12; j++)
            c[((size_t)b*MEM_ + m)*C_ + h*D_ + dg*12 + j] = acc[j];
    }
}

// ==================== host orchestration ====================
#define SMEM128 (GS * (128*128 + 16384))   // 98304
#define SMEM64  (GS * (64*128 + 16384))    // 73728

static void gemmA(const uint16_t* a, const uint16_t* w, const float* bias,
                  float* out, int M, int N, int K)
{
    int K3 = 3 * K;
    if (N >= 1536) {
        dim3 g(N / 128, (M + 127) / 128);
        gemm_mma<128><<<g, 256, SMEM128>>>((const bf16*)a, (const bf16*)w, bias, out, M, N, K3, 0);
    } else {
        dim3 g(N / 128, (M + 63) / 64);
        gemm_mma<64><<<g, 256, SMEM64>>>((const bf16*)a, (const bf16*)w, bias, out, M, N, K3, 0);
    }
}
static void gemmA_act(const uint16_t* a, const uint16_t* w, const float* bias,
                      float* out, int M, int N, int K)
{
    int K3 = 3 * K;
    if (N >= 1536) {
        dim3 g(N / 128, (M + 127) / 128);
        gemm_mma<128><<<g, 256, SMEM128>>>((const bf16*)a, (const bf16*)w, bias, out, M, N, K3, 1);
    } else {
        dim3 g(N / 128, (M + 63) / 64);
        gemm_mma<64><<<g, 256, SMEM64>>>((const bf16*)a, (const bf16*)w, bias, out, M, N, K3, 1);
    }
}
static void cvt(const float* x, uint16_t* aug, int rows, int K)
{
    int n = rows * (K >> 2);
    cvt_split<<<(n + 255) / 256, 256>>>(x, aug, rows, K);
}

extern "C" void kernel_launch(void* const* d_in, const int* in_sizes, int n_in,
                              void* d_out, int out_size)
{
    const float* cur_fea = (const float*)d_in[0];
    const float* n1w = (const float*)d_in[1];
    const float* n1b = (const float*)d_in[2];
    const float* n2w = (const float*)d_in[3];
    const float* n2b = (const float*)d_in[4];
    const float* c_w1 = (const float*)d_in[5];  const float* c_b1 = (const float*)d_in[6];
    const float* c_w2 = (const float*)d_in[7];  const float* c_b2 = (const float*)d_in[8];
    const float* m_w1 = (const float*)d_in[9];  const float* m_b1 = (const float*)d_in[10];
    const float* m_w2 = (const float*)d_in[11]; const float* m_b2 = (const float*)d_in[12];
    const float* p_w1 = (const float*)d_in[13]; const float* p_b1 = (const float*)d_in[14];
    const float* p_w2 = (const float*)d_in[15]; const float* p_b2 = (const float*)d_in[16];
    const float* q_w = (const float*)d_in[17];  const float* q_b = (const float*)d_in[18];
    const float* k_w = (const float*)d_in[19];  const float* k_b = (const float*)d_in[20];

    cudaFuncSetAttribute(gemm_mma<128>, cudaFuncAttributeMaxDynamicSharedMemorySize, SMEM128);
    cudaFuncSetAttribute(gemm_mma<64>,  cudaFuncAttributeMaxDynamicSharedMemorySize, SMEM64);

    float *x, *cat, *hid, *cg, *memh, *qb, *kb, *o, *c, *c2, *gate, *ap, *memA, *memB;
    cudaGetSymbolAddress((void**)&x, g_x);       cudaGetSymbolAddress((void**)&cat, g_cat);
    cudaGetSymbolAddress((void**)&hid, g_hid);   cudaGetSymbolAddress((void**)&cg, g_cg);
    cudaGetSymbolAddress((void**)&memh, g_memh); cudaGetSymbolAddress((void**)&qb, g_q);
    cudaGetSymbolAddress((void**)&kb, g_kk);     cudaGetSymbolAddress((void**)&o, g_o);
    cudaGetSymbolAddress((void**)&c, g_c);       cudaGetSymbolAddress((void**)&c2, g_c2);
    cudaGetSymbolAddress((void**)&gate, g_gate); cudaGetSymbolAddress((void**)&ap, g_ap);
    cudaGetSymbolAddress((void**)&memA, g_memA); cudaGetSymbolAddress((void**)&memB, g_memB);

    uint16_t *aBig, *aSm, *wc1, *wc2, *wm1, *wm2, *wp1, *wp2, *wq, *wk;
    cudaGetSymbolAddress((void**)&aBig, g_aBig); cudaGetSymbolAddress((void**)&aSm, g_aSm);
    cudaGetSymbolAddress((void**)&wc1, g_wc1);   cudaGetSymbolAddress((void**)&wc2, g_wc2);
    cudaGetSymbolAddress((void**)&wm1, g_wm1);   cudaGetSymbolAddress((void**)&wm2, g_wm2);
    cudaGetSymbolAddress((void**)&wp1, g_wp1);   cudaGetSymbolAddress((void**)&wp2, g_wp2);
    cudaGetSymbolAddress((void**)&wq, g_wq);     cudaGetSymbolAddress((void**)&wk, g_wk);

    // weight aug conversion (once per launch)
    dim3 wb(32, 8);
    wsplitT<<<dim3(HID_/32, (2*C_)/32), wb>>>(c_w1, wc1, 2*C_, HID_);
    wsplitT<<<dim3(C_/32, HID_/32),    wb>>>(c_w2, wc2, HID_, C_);
    wsplitT<<<dim3(HID_/32, C_/32),    wb>>>(m_w1, wm1, C_, HID_);
    wsplitT<<<dim3(C_/32, HID_/32),    wb>>>(m_w2, wm2, HID_, C_);
    wsplitT<<<dim3(HID_/32, C_/32),    wb>>>(p_w1, wp1, C_, HID_);
    wsplitT<<<dim3(C_/32, HID_/32),    wb>>>(p_w2, wp2, HID_, C_);
    wsplitT<<<dim3(C_/32, C_/32),      wb>>>(q_w, wq, C_, C_);
    wsplitT<<<dim3(C_/32, C_/32),      wb>>>(k_w, wk, C_, C_);

    ln_kernel<<<B_*T_*N_, 256>>>(cur_fea, n1w, n1b, x);
    initmem_kernel<<<(B_*MEM_*C_ + 255)/256, 256>>>(x, memA);

    float* mcur = memA;
    float* mnxt = memB;

    for (int t = 1; t < T_; t++) {
        ap_kernel<<<(B_*C_ + 255)/256, 256>>>(mcur, ap);
        cat_kernel<<<(ROWS_*2*C_ + 255)/256, 256>>>(x, ap, cat, t);

        cvt(cat, aBig, ROWS_, 2*C_);
        gemmA_act(aBig, wc1, c_b1, hid, ROWS_, HID_, 2*C_);     // fc1_c + gelu
        cvt(hid, aBig, ROWS_, HID_);
        gemmA(aBig, wc2, c_b2, cg, ROWS_, C_, HID_);            // fc2_c

        cvt(mcur, aSm, ROWS_, C_);
        gemmA_act(aSm, wm1, m_b1, hid, ROWS_, HID_, C_);        // fc1_m + gelu
        gemmA(aSm, wk, k_b, kb, ROWS_, C_, C_);                 // k = mem @ k_w
        cvt(hid, aBig, ROWS_, HID_);
        gemmA(aBig, wm2, m_b2, memh, ROWS_, C_, HID_);          // fc2_m

        cvt(cg, aSm, ROWS_, C_);
        gemmA(aSm, wq, q_b, qb, ROWS_, C_, C_);                 // q = cg @ q_w

        attn_kernel<<<dim3(7, 7, B_*H_), 256>>>(qb, kb, o);
        gate_kernel<<<(B_*H_*MEM_ + 255)/256, 256>>>(o, gate);
        cgather_kernel<<<dim3(7, B_*H_), 256>>>(o, cg, c);

        cvt(c, aSm, ROWS_, C_);
        gemmA_act(aSm, wp1, p_b1, hid, ROWS_, HID_, C_);        // fc1_p + gelu
        cvt(hid, aBig, ROWS_, HID_);
        gemmA(aBig, wp2, p_b2, c2, ROWS_, C_, HID_);            // fc2_p

        float* dst = (t == T_ - 1) ? (float*)d_out : mnxt;
        final_kernel<<<B_*MEM_, 256>>>(c2, gate, memh, n2w, n2b, dst);

        float* tmp = mcur; mcur = mnxt; mnxt = tmp;
    }
}

// round 5
// speedup vs baseline: 2.0619x; 1.2100x over previous
#include <cuda_runtime.h>
#include <cuda_bf16.h>
#include <math.h>
#include <stdint.h>

#define B_   8
#define T_   16
#define N_   196
#define C_   768
#define H_   8
#define D_   96
#define MEM_ 196
#define HID_ 3072
#define ROWS_ 1568
#define SCALE_ 0.1020620726159657f

typedef __nv_bfloat16 bf16;

// ---------------- fp32 scratch ----------------
__device__ __align__(256) float g_x   [B_*T_*N_*C_];
__device__ __align__(256) float g_cg  [ROWS_*C_];
__device__ __align__(256) float g_memh[ROWS_*C_];
__device__ __align__(256) float g_q   [ROWS_*C_];
__device__ __align__(256) float g_kk  [ROWS_*C_];
__device__ __align__(256) float g_o   [B_*H_*N_*MEM_];
__device__ __align__(256) float g_c2  [ROWS_*C_];
__device__ __align__(256) float g_gate[B_*H_*MEM_];
__device__ __align__(256) float g_ap  [B_*C_];
__device__ __align__(256) float g_memA[ROWS_*C_];
__device__ __align__(256) float g_memB[ROWS_*C_];

// ---------------- augmented bf16 activations [rows][3K] = [hi|hi|lo] ----------------
__device__ __align__(256) uint16_t g_hidA[ROWS_*3*HID_];
__device__ __align__(256) uint16_t g_catA[ROWS_*3*2*C_];
__device__ __align__(256) uint16_t g_cgA [ROWS_*3*C_];
__device__ __align__(256) uint16_t g_cA  [ROWS_*3*C_];
__device__ __align__(256) uint16_t g_memAg[ROWS_*3*C_];

// weights augmented [N][3K] = [hi|lo|hi]
__device__ __align__(256) uint16_t g_wc1[HID_*3*2*C_];
__device__ __align__(256) uint16_t g_wc2[C_*3*HID_];
__device__ __align__(256) uint16_t g_wm1[HID_*3*C_];
__device__ __align__(256) uint16_t g_wm2[C_*3*HID_];
__device__ __align__(256) uint16_t g_wp1[HID_*3*C_];
__device__ __align__(256) uint16_t g_wp2[C_*3*HID_];
__device__ __align__(256) uint16_t g_wq [C_*3*C_];
__device__ __align__(256) uint16_t g_wk [C_*3*C_];

__device__ __forceinline__ float gelu_exact(float x) {
    return 0.5f * x * (1.0f + erff(x * 0.70710678118654752f));
}
__device__ __forceinline__ uint32_t smem_u32(const void* p) {
    uint32_t a;
    asm("{ .reg .u64 t; cvta.to.shared.u64 t, %1; cvt.u32.u64 %0, t; }" : "=r"(a) : "l"(p));
    return a;
}
__device__ __forceinline__ void cp16(uint32_t dst, const void* src, int pred) {
    int sz = pred ? 16 : 0;
    asm volatile("cp.async.cg.shared.global [%0], [%1], 16, %2;" :: "r"(dst), "l"(src), "r"(sz) : "memory");
}
__device__ __forceinline__ uint32_t swz(uint32_t o) { return o ^ ((o >> 3) & 0x70); }

#define LDSM4(r0, r1, r2, r3, addr) \
    asm volatile("ldmatrix.sync.aligned.m8n8.x4.shared.b16 {%0,%1,%2,%3}, [%4];" \
        : "=r"(r0), "=r"(r1), "=r"(r2), "=r"(r3) : "r"(addr))

#define MMA16816(d, a, b0, b1) \
    asm volatile("mma.sync.aligned.m16n8k16.row.col.f32.bf16.bf16.f32 " \
        "{%0,%1,%2,%3}, {%4,%5,%6,%7}, {%8,%9}, {%0,%1,%2,%3};" \
        : "+f"((d)[0]), "+f"((d)[1]), "+f"((d)[2]), "+f"((d)[3]) \
        : "r"((a)[0]), "r"((a)[1]), "r"((a)[2]), "r"((a)[3]), "r"(b0), "r"(b1))

// pack two floats into aug slots: hi at base+col & base+N+col, lo at base+2N+col
__device__ __forceinline__ void aug_store(uint16_t* aug, size_t base, int Ncols, int col,
                                          float v0, float v1)
{
    bf16 h0 = __float2bfloat16(v0), h1 = __float2bfloat16(v1);
    __nv_bfloat162 hh = __halves2bfloat162(h0, h1);
    __nv_bfloat162 ll = __halves2bfloat162(__float2bfloat16(v0 - __bfloat162float(h0)),
                                           __float2bfloat16(v1 - __bfloat162float(h1)));
    *(uint32_t*)(aug + base + col)             = *(uint32_t*)&hh;
    *(uint32_t*)(aug + base + Ncols + col)     = *(uint32_t*)&hh;
    *(uint32_t*)(aug + base + 2 * Ncols + col) = *(uint32_t*)&ll;
}

// ==================== bf16 mma.sync GEMM ====================
// mode bits: 1=gelu, 2=write fp32 out, 4=write aug [hi|hi|lo]
#define GS 3

template<int BM, int BN, int MT, int NT>
__global__ __launch_bounds__(256) void gemm_mma(
    const bf16* __restrict__ A, const bf16* __restrict__ Bw,
    const float* __restrict__ bias, float* __restrict__ out,
    uint16_t* __restrict__ outAug, int M, int N, int K3, int mode)
{
    constexpr int A_BYTES = BM * 128;
    constexpr int STG = (BM + BN) * 128;
    extern __shared__ __align__(1024) char smem[];
    uint32_t sb = smem_u32(smem);
    int tid = threadIdx.x, wid = tid >> 5, lane = tid & 31;
    int bm = blockIdx.y * BM, bn = blockIdx.x * BN;
    int m0w = (wid & 1) * (MT * 16);
    int n0w = (wid >> 1) * (NT * 8);
    int NC = K3 >> 6;

    auto load_stage = [&](int c) {
        uint32_t stage = sb + (c % GS) * STG;
        int k0 = c << 6;
        constexpr int TOT = (BM + BN) * 8;
#pragma unroll
        for (int g0 = 0; g0 < TOT; g0 += 256) {
            int g = g0 + tid;
            int isB = (g >= BM * 8);
            int q = isB ? (g - BM * 8) : g;
            int row = q >> 3, c16 = q & 7;
            uint32_t dst = stage + (isB ? A_BYTES : 0) + swz((row << 7) + (c16 << 4));
            const bf16* src;
            int pred = 1;
            if (!isB) {
                int gr = bm + row; pred = gr < M;
                src = A + (size_t)(pred ? gr : 0) * K3 + k0 + (c16 << 3);
            } else {
                int gr = bn + row;
                src = Bw + (size_t)gr * K3 + k0 + (c16 << 3);
            }
            cp16(dst, src, pred);
        }
        asm volatile("cp.async.commit_group;" ::: "memory");
    };

    float acc[MT][NT][4];
#pragma unroll
    for (int mt = 0; mt < MT; mt++)
#pragma unroll
        for (int nt = 0; nt < NT; nt++)
#pragma unroll
            for (int i = 0; i < 4; i++) acc[mt][nt][i] = 0.f;

    load_stage(0);
    load_stage(1);

    for (int c = 0; c < NC; c++) {
        if (c == NC - 1) asm volatile("cp.async.wait_group 0;" ::: "memory");
        else             asm volatile("cp.async.wait_group 1;" ::: "memory");
        __syncthreads();
        if (c + 2 < NC) load_stage(c + 2);

        uint32_t sA = sb + (c % GS) * STG;
        uint32_t sB = sA + A_BYTES;
#pragma unroll
        for (int ks = 0; ks < 4; ks++) {
            uint32_t a[MT][4], bfr[NT / 2][4];
#pragma unroll
            for (int mt = 0; mt < MT; mt++) {
                int row = m0w + mt * 16 + (lane & 15);
                int ch = ks * 2 + (lane >> 4);
                uint32_t ad = sA + swz((uint32_t)(row << 7) + (ch << 4));
                LDSM4(a[mt][0], a[mt][1], a[mt][2], a[mt][3], ad);
            }
#pragma unroll
            for (int bp = 0; bp < NT / 2; bp++) {
                int row = n0w + bp * 16 + (lane & 7) + ((lane & 16) >> 1);
                int ch = ks * 2 + ((lane & 8) >> 3);
                uint32_t ad = sB + swz((uint32_t)(row << 7) + (ch << 4));
                LDSM4(bfr[bp][0], bfr[bp][1], bfr[bp][2], bfr[bp][3], ad);
            }
#pragma unroll
            for (int mt = 0; mt < MT; mt++)
#pragma unroll
                for (int nt = 0; nt < NT; nt++)
                    MMA16816(acc[mt][nt], a[mt],
                             bfr[nt >> 1][(nt & 1) * 2], bfr[nt >> 1][(nt & 1) * 2 + 1]);
        }
    }

    // epilogue: bias [+gelu] [+fp32] [+aug]
#pragma unroll
    for (int mt = 0; mt < MT; mt++) {
        int r0 = bm + m0w + mt * 16 + (lane >> 2);
        int r1 = r0 + 8;
#pragma unroll
        for (int nt = 0; nt < NT; nt++) {
            int col = bn + n0w + nt * 8 + ((lane & 3) << 1);
            float bv0 = bias[col], bv1 = bias[col + 1];
            float v0 = acc[mt][nt][0] + bv0, v1 = acc[mt][nt][1] + bv1;
            float v2 = acc[mt][nt][2] + bv0, v3 = acc[mt][nt][3] + bv1;
            if (mode & 1) {
                v0 = gelu_exact(v0); v1 = gelu_exact(v1);
                v2 = gelu_exact(v2); v3 = gelu_exact(v3);
            }
            if (r0 < M) {
                if (mode & 2) *(float2*)(out + (size_t)r0 * N + col) = make_float2(v0, v1);
                if (mode & 4) aug_store(outAug, (size_t)r0 * 3 * N, N, col, v0, v1);
            }
            if (r1 < M) {
                if (mode & 2) *(float2*)(out + (size_t)r1 * N + col) = make_float2(v2, v3);
                if (mode & 4) aug_store(outAug, (size_t)r1 * 3 * N, N, col, v2, v3);
            }
        }
    }
}

// W [K][N] fp32 -> aug bf16 [N][3K] = [hi|lo|hi]
__global__ void wsplitT(const float* __restrict__ w, uint16_t* __restrict__ aug,
                        int K, int N)
{
    __shared__ float t[32][33];
    int n0 = blockIdx.x * 32, k0 = blockIdx.y * 32;
    int tx = threadIdx.x, ty = threadIdx.y;
#pragma unroll
    for (int j = 0; j < 4; j++)
        t[ty + 8 * j][tx] = w[(size_t)(k0 + ty + 8 * j) * N + n0 + tx];
    __syncthreads();
#pragma unroll
    for (int j = 0; j < 4; j++) {
        float v = t[tx][ty + 8 * j];
        int n = n0 + ty + 8 * j, k = k0 + tx;
        bf16 h = __float2bfloat16(v);
        bf16 l = __float2bfloat16(v - __bfloat162float(h));
        size_t base = (size_t)n * 3 * K;
        *(bf16*)(aug + base + k)         = h;
        *(bf16*)(aug + base + K + k)     = l;   // pairs with A's 2nd hi
        *(bf16*)(aug + base + 2 * K + k) = h;   // pairs with A's lo
    }
}

// ==================== fused elementwise kernels ====================
__global__ __launch_bounds__(256) void ln_kernel(
    const float* __restrict__ x, const float* __restrict__ w,
    const float* __restrict__ b, float* __restrict__ y)
{
    int row = blockIdx.x;
    const float* xr = x + (size_t)row * C_;
    float v[3], s = 0.f, s2 = 0.f;
#pragma unroll
    for (int i = 0; i < 3; i++) { v[i] = xr[threadIdx.x + i*256]; s += v[i]; s2 += v[i]*v[i]; }
    __shared__ float red[18];
#pragma unroll
    for (int off = 16; off; off >>= 1) {
        s  += __shfl_down_sync(0xffffffffu, s, off);
        s2 += __shfl_down_sync(0xffffffffu, s2, off);
    }
    int wid = threadIdx.x >> 5, lane = threadIdx.x & 31;
    if (lane == 0) { red[wid] = s; red[8+wid] = s2; }
    __syncthreads();
    if (threadIdx.x == 0) {
        float ts = 0.f, ts2 = 0.f;
        for (int i = 0; i < 8; i++) { ts += red[i]; ts2 += red[8+i]; }
        red[16] = ts; red[17] = ts2;
    }
    __syncthreads();
    float mean = red[16] * (1.0f/C_);
    float inv  = rsqrtf(red[17] * (1.0f/C_) - mean*mean + 1e-5f);
    float* yr = y + (size_t)row * C_;
#pragma unroll
    for (int i = 0; i < 3; i++) {
        int c = threadIdx.x + i*256;
        yr[c] = (v[i] - mean) * inv * w[c] + b[c];
    }
}

// final: LN(c2 + gate*memh) -> fp32 y AND aug memAug
__global__ __launch_bounds__(256) void final_kernel(
    const float* __restrict__ c2, const float* __restrict__ gate,
    const float* __restrict__ memh, const float* __restrict__ w,
    const float* __restrict__ bb, float* __restrict__ y, uint16_t* __restrict__ aug)
{
    int row = blockIdx.x;
    int b = row / MEM_, m = row % MEM_;
    float v[3], s = 0.f, s2 = 0.f;
#pragma unroll
    for (int i = 0; i < 3; i++) {
        int c = threadIdx.x + i*256;
        float g = gate[(b*H_ + (c/D_))*MEM_ + m];
        v[i] = c2[(size_t)row*C_ + c] + g * memh[(size_t)row*C_ + c];
        s += v[i]; s2 += v[i]*v[i];
    }
    __shared__ float red[18];
#pragma unroll
    for (int off = 16; off; off >>= 1) {
        s  += __shfl_down_sync(0xffffffffu, s, off);
        s2 += __shfl_down_sync(0xffffffffu, s2, off);
    }
    int wid = threadIdx.x >> 5, lane = threadIdx.x & 31;
    if (lane == 0) { red[wid] = s; red[8+wid] = s2; }
    __syncthreads();
    if (threadIdx.x == 0) {
        float ts = 0.f, ts2 = 0.f;
        for (int i = 0; i < 8; i++) { ts += red[i]; ts2 += red[8+i]; }
        red[16] = ts; red[17] = ts2;
    }
    __syncthreads();
    float mean = red[16] * (1.0f/C_);
    float inv  = rsqrtf(red[17] * (1.0f/C_) - mean*mean + 1e-5f);
    float* yr = y + (size_t)row * C_;
    size_t base = (size_t)row * 3 * C_;
#pragma unroll
    for (int i = 0; i < 3; i++) {
        int c = threadIdx.x + i*256;
        float o = (v[i] - mean) * inv * w[c] + bb[c];
        yr[c] = o;
        bf16 h = __float2bfloat16(o);
        aug[base + c]        = *(uint16_t*)&h;
        aug[base + C_ + c]   = *(uint16_t*)&h;
        bf16 l = __float2bfloat16(o - __bfloat162float(h));
        aug[base + 2*C_ + c] = *(uint16_t*)&l;
    }
}

// init mem = frame 0 of LN'd x: fp32 + aug
__global__ void initmem_kernel(const float* __restrict__ x, float* __restrict__ mem,
                               uint16_t* __restrict__ aug)
{
    int idx = blockIdx.x * 256 + threadIdx.x;   // pair index
    if (idx >= B_*MEM_*C_/2) return;
    int row = idx / (C_/2), jp = (idx % (C_/2)) * 2;
    int b = row / MEM_, r = row % MEM_;
    float2 v = *(const float2*)(x + (size_t)b*T_*N_*C_ + (size_t)r*C_ + jp);
    *(float2*)(mem + (size_t)row*C_ + jp) = v;
    aug_store(aug, (size_t)row * 3 * C_, C_, jp, v.x, v.y);
}

__global__ void ap_kernel(const float* __restrict__ mem, float* __restrict__ ap)
{
    int idx = blockIdx.x * 256 + threadIdx.x;
    if (idx >= B_*C_) return;
    int b = idx / C_, c = idx % C_;
    float s = 0.f;
    const float* p = mem + (size_t)b*MEM_*C_ + c;
    for (int m = 0; m < MEM_; m++) s += p[(size_t)m*C_];
    ap[idx] = s * (1.0f/MEM_);
}

// cat -> aug directly: row j<768 from x(t), else ap
__global__ void cat_aug_kernel(const float* __restrict__ x, const float* __restrict__ ap,
                               uint16_t* __restrict__ aug, int t)
{
    int idx = blockIdx.x * 256 + threadIdx.x;   // pair index over ROWS*768
    if (idx >= ROWS_ * 768) return;
    int row = idx / 768, jp = (idx % 768) * 2;
    int b = row / N_, n = row % N_;
    float2 v;
    if (jp < C_) v = *(const float2*)(x + (((size_t)b*T_ + t)*N_ + n)*C_ + jp);
    else         v = *(const float2*)(ap + b*C_ + jp - C_);
    aug_store(aug, (size_t)row * 3 * (2*C_), 2*C_, jp, v.x, v.y);
}

__global__ __launch_bounds__(256) void attn_kernel(
    const float* __restrict__ q, const float* __restrict__ k, float* __restrict__ o)
{
    int bh = blockIdx.z, b = bh >> 3, h = bh & 7;
    int m0 = blockIdx.x * 32, n0 = blockIdx.y * 32;
    __shared__ float Qs[32][97];
    __shared__ float Ks[32][97];
    for (int idx = threadIdx.x; idx < 32*96; idx += 256) {
        int r = idx / 96, d = idx % 96;
        int n = n0 + r;
        Qs[r][d] = (n < N_) ? q[((size_t)b*N_ + n)*C_ + h*D_ + d] : 0.f;
        int m = m0 + r;
        Ks[r][d] = (m < MEM_) ? k[((size_t)b*MEM_ + m)*C_ + h*D_ + d] : 0.f;
    }
    __syncthreads();
    int nl = threadIdx.x & 31, mg = threadIdx.x >> 5;
    float acc[4] = {0.f, 0.f, 0.f, 0.f};
    for (int d = 0; d < 96; d++) {
        float qv = Qs[nl][d];
#pragma unroll
        for (int i = 0; i < 4; i++) acc[i] = fmaf(qv, Ks[mg*4 + i][d], acc[i]);
    }
    int n = n0 + nl;
    if (n < N_) {
#pragma unroll
        for (int i = 0; i < 4; i++) {
            int m = m0 + mg*4 + i;
            if (m < MEM_)
                o[(((size_t)b*H_ + h)*N_ + n)*MEM_ + m] = 1.0f / (1.0f + expf(-acc[i]*SCALE_));
        }
    }
}

__global__ void gate_kernel(const float* __restrict__ o, float* __restrict__ gate)
{
    int idx = blockIdx.x * 256 + threadIdx.x;
    if (idx >= B_*H_*MEM_) return;
    int m = idx % MEM_, bh = idx / MEM_;
    const float* op = o + (size_t)bh*N_*MEM_ + m;
    float s = 0.f;
    for (int n = 0; n < N_; n++) s += op[(size_t)n*MEM_];
    gate[idx] = 1.0f - s * (1.0f/N_);
}

// c = einsum(o, cg) written directly as aug bf16
__global__ __launch_bounds__(256) void cgather_kernel(
    const float* __restrict__ o, const float* __restrict__ cg, uint16_t* __restrict__ cAug)
{
    int bh = blockIdx.y, b = bh >> 3, h = bh & 7;
    int m0 = blockIdx.x * 32;
    int ml = threadIdx.x & 31, dg = threadIdx.x >> 5;
    __shared__ float Os[32][33];
    __shared__ float Gs[32][97];
    float acc[12];
#pragma unroll
    for (int j = 0; j < 12; j++) acc[j] = 0.f;
    for (int n0 = 0; n0 < N_; n0 += 32) {
        for (int idx = threadIdx.x; idx < 32*32; idx += 256) {
            int r = idx >> 5, cc = idx & 31;
            int n = n0 + r, m = m0 + cc;
            Os[r][cc] = (n < N_ && m < MEM_) ? o[(((size_t)b*H_ + h)*N_ + n)*MEM_ + m] : 0.f;
        }
        for (int idx = threadIdx.x; idx < 32*96; idx += 256) {
            int r = idx / 96, d = idx % 96;
            int n = n0 + r;
            Gs[r][d] = (n < N_) ? cg[((size_t)b*N_ + n)*C_ + h*D_ + d] : 0.f;
        }
        __syncthreads();
#pragma unroll 8
        for (int nn = 0; nn < 32; nn++) {
            float ov = Os[nn][ml];
#pragma unroll
            for (int j = 0; j < 12; j++) acc[j] = fmaf(ov, Gs[nn][dg*12 + j], acc[j]);
        }
        __syncthreads();
    }
    int m = m0 + ml;
    if (m < MEM_) {
        size_t base = ((size_t)b*MEM_ + m) * 3 * C_;
        int col0 = h*D_ + dg*12;
#pragma unroll
        for (int j = 0; j < 12; j += 2)
            aug_store(cAug, base, C_, col0 + j, acc[j], acc[j+1]);
    }
}

// ==================== host orchestration ====================
#define SMEM_BIG (GS * (128 + 256) * 128)   // 147456
#define SMEM_SM  (GS * (64 + 128) * 128)    // 73728

static void gemm_big(const uint16_t* a, const uint16_t* w, const float* bias,
                     float* out, uint16_t* outAug, int M, int N, int K, int mode)
{
    dim3 g(N / 256, (M + 127) / 128);
    gemm_mma<128, 256, 4, 8><<<g, 256, SMEM_BIG>>>(
        (const bf16*)a, (const bf16*)w, bias, out, outAug, M, N, 3 * K, mode);
}
static void gemm_sm(const uint16_t* a, const uint16_t* w, const float* bias,
                    float* out, uint16_t* outAug, int M, int N, int K, int mode)
{
    dim3 g(N / 128, (M + 63) / 64);
    gemm_mma<64, 128, 2, 4><<<g, 256, SMEM_SM>>>(
        (const bf16*)a, (const bf16*)w, bias, out, outAug, M, N, 3 * K, mode);
}

extern "C" void kernel_launch(void* const* d_in, const int* in_sizes, int n_in,
                              void* d_out, int out_size)
{
    const float* cur_fea = (const float*)d_in[0];
    const float* n1w = (const float*)d_in[1];
    const float* n1b = (const float*)d_in[2];
    const float* n2w = (const float*)d_in[3];
    const float* n2b = (const float*)d_in[4];
    const float* c_w1 = (const float*)d_in[5];  const float* c_b1 = (const float*)d_in[6];
    const float* c_w2 = (const float*)d_in[7];  const float* c_b2 = (const float*)d_in[8];
    const float* m_w1 = (const float*)d_in[9];  const float* m_b1 = (const float*)d_in[10];
    const float* m_w2 = (const float*)d_in[11]; const float* m_b2 = (const float*)d_in[12];
    const float* p_w1 = (const float*)d_in[13]; const float* p_b1 = (const float*)d_in[14];
    const float* p_w2 = (const float*)d_in[15]; const float* p_b2 = (const float*)d_in[16];
    const float* q_w = (const float*)d_in[17];  const float* q_b = (const float*)d_in[18];
    const float* k_w = (const float*)d_in[19];  const float* k_b = (const float*)d_in[20];

    cudaFuncSetAttribute((const void*)gemm_mma<128, 256, 4, 8>,
                         cudaFuncAttributeMaxDynamicSharedMemorySize, SMEM_BIG);
    cudaFuncSetAttribute((const void*)gemm_mma<64, 128, 2, 4>,
                         cudaFuncAttributeMaxDynamicSharedMemorySize, SMEM_SM);

    float *x, *cg, *memh, *qb, *kb, *o, *c2, *gate, *ap, *memA, *memB;
    cudaGetSymbolAddress((void**)&x, g_x);       cudaGetSymbolAddress((void**)&cg, g_cg);
    cudaGetSymbolAddress((void**)&memh, g_memh); cudaGetSymbolAddress((void**)&qb, g_q);
    cudaGetSymbolAddress((void**)&kb, g_kk);     cudaGetSymbolAddress((void**)&o, g_o);
    cudaGetSymbolAddress((void**)&c2, g_c2);     cudaGetSymbolAddress((void**)&gate, g_gate);
    cudaGetSymbolAddress((void**)&ap, g_ap);
    cudaGetSymbolAddress((void**)&memA, g_memA); cudaGetSymbolAddress((void**)&memB, g_memB);

    uint16_t *hidA, *catA, *cgA, *cA, *memAg;
    uint16_t *wc1, *wc2, *wm1, *wm2, *wp1, *wp2, *wq, *wk;
    cudaGetSymbolAddress((void**)&hidA, g_hidA); cudaGetSymbolAddress((void**)&catA, g_catA);
    cudaGetSymbolAddress((void**)&cgA, g_cgA);   cudaGetSymbolAddress((void**)&cA, g_cA);
    cudaGetSymbolAddress((void**)&memAg, g_memAg);
    cudaGetSymbolAddress((void**)&wc1, g_wc1);   cudaGetSymbolAddress((void**)&wc2, g_wc2);
    cudaGetSymbolAddress((void**)&wm1, g_wm1);   cudaGetSymbolAddress((void**)&wm2, g_wm2);
    cudaGetSymbolAddress((void**)&wp1, g_wp1);   cudaGetSymbolAddress((void**)&wp2, g_wp2);
    cudaGetSymbolAddress((void**)&wq, g_wq);     cudaGetSymbolAddress((void**)&wk, g_wk);

    // weight aug conversion (once per launch)
    dim3 wb(32, 8);
    wsplitT<<<dim3(HID_/32, (2*C_)/32), wb>>>(c_w1, wc1, 2*C_, HID_);
    wsplitT<<<dim3(C_/32, HID_/32),    wb>>>(c_w2, wc2, HID_, C_);
    wsplitT<<<dim3(HID_/32, C_/32),    wb>>>(m_w1, wm1, C_, HID_);
    wsplitT<<<dim3(C_/32, HID_/32),    wb>>>(m_w2, wm2, HID_, C_);
    wsplitT<<<dim3(HID_/32, C_/32),    wb>>>(p_w1, wp1, C_, HID_);
    wsplitT<<<dim3(C_/32, HID_/32),    wb>>>(p_w2, wp2, HID_, C_);
    wsplitT<<<dim3(C_/32, C_/32),      wb>>>(q_w, wq, C_, C_);
    wsplitT<<<dim3(C_/32, C_/32),      wb>>>(k_w, wk, C_, C_);

    ln_kernel<<<B_*T_*N_, 256>>>(cur_fea, n1w, n1b, x);
    initmem_kernel<<<(B_*MEM_*C_/2 + 255)/256, 256>>>(x, memA, memAg);

    float* mcur = memA;
    float* mnxt = memB;

    for (int t = 1; t < T_; t++) {
        ap_kernel<<<(B_*C_ + 255)/256, 256>>>(mcur, ap);
        cat_aug_kernel<<<(ROWS_*768 + 255)/256, 256>>>(x, ap, catA, t);

        gemm_big(catA, wc1, c_b1, nullptr, hidA, ROWS_, HID_, 2*C_, 1|4);  // fc1_c: gelu->aug
        gemm_sm (hidA, wc2, c_b2, cg, cgA, ROWS_, C_, HID_, 2|4);          // fc2_c: fp32+aug
        gemm_big(memAg, wm1, m_b1, nullptr, hidA, ROWS_, HID_, C_, 1|4);   // fc1_m: gelu->aug
        gemm_sm (hidA, wm2, m_b2, memh, nullptr, ROWS_, C_, HID_, 2);      // fc2_m
        gemm_sm (memAg, wk, k_b, kb, nullptr, ROWS_, C_, C_, 2);           // k = mem @ k_w
        gemm_sm (cgA, wq, q_b, qb, nullptr, ROWS_, C_, C_, 2);             // q = cg @ q_w

        attn_kernel<<<dim3(7, 7, B_*H_), 256>>>(qb, kb, o);
        gate_kernel<<<(B_*H_*MEM_ + 255)/256, 256>>>(o, gate);
        cgather_kernel<<<dim3(7, B_*H_), 256>>>(o, cg, cA);

        gemm_big(cA, wp1, p_b1, nullptr, hidA, ROWS_, HID_, C_, 1|4);      // fc1_p: gelu->aug
        gemm_sm (hidA, wp2, p_b2, c2, nullptr, ROWS_, C_, HID_, 2);        // fc2_p

        float* dst = (t == T_ - 1) ? (float*)d_out : mnxt;
        final_kernel<<<B_*MEM_, 256>>>(c2, gate, memh, n2w, n2b, dst, memAg);

        float* tmp = mcur; mcur = mnxt; mnxt = tmp;
    }
}

// round 6
// speedup vs baseline: 2.1502x; 1.0428x over previous
#include <cuda_runtime.h>
#include <cuda_bf16.h>
#include <math.h>
#include <stdint.h>

#define B_   8
#define T_   16
#define N_   196
#define C_   768
#define H_   8
#define D_   96
#define MEM_ 196
#define HID_ 3072
#define ROWS_ 1568
#define SCALE_ 0.1020620726159657f

typedef __nv_bfloat16 bf16;

// ---------------- fp32 scratch ----------------
__device__ __align__(256) float g_x   [B_*T_*N_*C_];
__device__ __align__(256) float g_cg  [ROWS_*C_];
__device__ __align__(256) float g_memh[ROWS_*C_];
__device__ __align__(256) float g_q   [ROWS_*C_];
__device__ __align__(256) float g_kk  [ROWS_*C_];
__device__ __align__(256) float g_o   [B_*H_*N_*MEM_];
__device__ __align__(256) float g_c2  [ROWS_*C_];
__device__ __align__(256) float g_gate[B_*H_*MEM_];
__device__ __align__(256) float g_ap  [B_*C_];
__device__ __align__(256) float g_memA[ROWS_*C_];
__device__ __align__(256) float g_memB[ROWS_*C_];

// ---------------- augmented bf16 activations ----------------
__device__ __align__(256) uint16_t g_hidA[ROWS_*3*HID_];
__device__ __align__(256) uint16_t g_catA[ROWS_*3*2*C_];
__device__ __align__(256) uint16_t g_cgA [ROWS_*3*C_];
__device__ __align__(256) uint16_t g_cA  [ROWS_*3*C_];
__device__ __align__(256) uint16_t g_memAg[ROWS_*3*C_];

// attention aug operands
__device__ __align__(256) uint16_t g_Q3 [64*196*384];   // [bh][n][s*128+d], hi|hi|lo
__device__ __align__(256) uint16_t g_K3 [64*196*384];   // [bh][m][s*128+d], hi|lo|hi
__device__ __align__(256) uint16_t g_oT3[64*196*768];   // [bh][m][s*256+n], hi|hi|lo
__device__ __align__(256) uint16_t g_cgT3[64*96*768];   // [bh][d][s*256+n], hi|lo|hi

// weights augmented [N][3K] = [hi|lo|hi]
__device__ __align__(256) uint16_t g_wc1[HID_*3*2*C_];
__device__ __align__(256) uint16_t g_wc2[C_*3*HID_];
__device__ __align__(256) uint16_t g_wm1[HID_*3*C_];
__device__ __align__(256) uint16_t g_wm2[C_*3*HID_];
__device__ __align__(256) uint16_t g_wp1[HID_*3*C_];
__device__ __align__(256) uint16_t g_wp2[C_*3*HID_];
__device__ __align__(256) uint16_t g_wq [C_*3*C_];
__device__ __align__(256) uint16_t g_wk [C_*3*C_];

__device__ __forceinline__ float gelu_exact(float x) {
    return 0.5f * x * (1.0f + erff(x * 0.70710678118654752f));
}
__device__ __forceinline__ uint32_t smem_u32(const void* p) {
    uint32_t a;
    asm("{ .reg .u64 t; cvta.to.shared.u64 t, %1; cvt.u32.u64 %0, t; }" : "=r"(a) : "l"(p));
    return a;
}
__device__ __forceinline__ void cp16(uint32_t dst, const void* src, int pred) {
    int sz = pred ? 16 : 0;
    asm volatile("cp.async.cg.shared.global [%0], [%1], 16, %2;" :: "r"(dst), "l"(src), "r"(sz) : "memory");
}
__device__ __forceinline__ uint32_t swz(uint32_t o) { return o ^ ((o >> 3) & 0x70); }

#define LDSM4(r0, r1, r2, r3, addr) \
    asm volatile("ldmatrix.sync.aligned.m8n8.x4.shared.b16 {%0,%1,%2,%3}, [%4];" \
        : "=r"(r0), "=r"(r1), "=r"(r2), "=r"(r3) : "r"(addr))

#define MMA16816(d, a, b0, b1) \
    asm volatile("mma.sync.aligned.m16n8k16.row.col.f32.bf16.bf16.f32 " \
        "{%0,%1,%2,%3}, {%4,%5,%6,%7}, {%8,%9}, {%0,%1,%2,%3};" \
        : "+f"((d)[0]), "+f"((d)[1]), "+f"((d)[2]), "+f"((d)[3]) \
        : "r"((a)[0]), "r"((a)[1]), "r"((a)[2]), "r"((a)[3]), "r"(b0), "r"(b1))

__device__ __forceinline__ void aug_store(uint16_t* aug, size_t base, int Ncols, int col,
                                          float v0, float v1)
{
    bf16 h0 = __float2bfloat16(v0), h1 = __float2bfloat16(v1);
    __nv_bfloat162 hh = __halves2bfloat162(h0, h1);
    __nv_bfloat162 ll = __halves2bfloat162(__float2bfloat16(v0 - __bfloat162float(h0)),
                                           __float2bfloat16(v1 - __bfloat162float(h1)));
    *(uint32_t*)(aug + base + col)             = *(uint32_t*)&hh;
    *(uint32_t*)(aug + base + Ncols + col)     = *(uint32_t*)&hh;
    *(uint32_t*)(aug + base + 2 * Ncols + col) = *(uint32_t*)&ll;
}

// ==================== weight-vs-activation GEMM (proven, R5) ====================
#define GS 3

template<int BM, int BN, int MT, int NT>
__global__ __launch_bounds__(256) void gemm_mma(
    const bf16* __restrict__ A, const bf16* __restrict__ Bw,
    const float* __restrict__ bias, float* __restrict__ out,
    uint16_t* __restrict__ outAug, int M, int N, int K3, int mode)
{
    constexpr int A_BYTES = BM * 128;
    constexpr int STG = (BM + BN) * 128;
    extern __shared__ __align__(1024) char smem[];
    uint32_t sb = smem_u32(smem);
    int tid = threadIdx.x, wid = tid >> 5, lane = tid & 31;
    int bm = blockIdx.y * BM, bn = blockIdx.x * BN;
    int m0w = (wid & 1) * (MT * 16);
    int n0w = (wid >> 1) * (NT * 8);
    int NC = K3 >> 6;

    auto load_stage = [&](int c) {
        uint32_t stage = sb + (c % GS) * STG;
        int k0 = c << 6;
        constexpr int TOT = (BM + BN) * 8;
#pragma unroll
        for (int g0 = 0; g0 < TOT; g0 += 256) {
            int g = g0 + tid;
            int isB = (g >= BM * 8);
            int q = isB ? (g - BM * 8) : g;
            int row = q >> 3, c16 = q & 7;
            uint32_t dst = stage + (isB ? A_BYTES : 0) + swz((row << 7) + (c16 << 4));
            const bf16* src;
            int pred = 1;
            if (!isB) {
                int gr = bm + row; pred = gr < M;
                src = A + (size_t)(pred ? gr : 0) * K3 + k0 + (c16 << 3);
            } else {
                int gr = bn + row;
                src = Bw + (size_t)gr * K3 + k0 + (c16 << 3);
            }
            cp16(dst, src, pred);
        }
        asm volatile("cp.async.commit_group;" ::: "memory");
    };

    float acc[MT][NT][4];
#pragma unroll
    for (int mt = 0; mt < MT; mt++)
#pragma unroll
        for (int nt = 0; nt < NT; nt++)
#pragma unroll
            for (int i = 0; i < 4; i++) acc[mt][nt][i] = 0.f;

    load_stage(0);
    load_stage(1);

    for (int c = 0; c < NC; c++) {
        if (c == NC - 1) asm volatile("cp.async.wait_group 0;" ::: "memory");
        else             asm volatile("cp.async.wait_group 1;" ::: "memory");
        __syncthreads();
        if (c + 2 < NC) load_stage(c + 2);

        uint32_t sA = sb + (c % GS) * STG;
        uint32_t sB = sA + A_BYTES;
#pragma unroll
        for (int ks = 0; ks < 4; ks++) {
            uint32_t a[MT][4], bfr[NT / 2][4];
#pragma unroll
            for (int mt = 0; mt < MT; mt++) {
                int row = m0w + mt * 16 + (lane & 15);
                int ch = ks * 2 + (lane >> 4);
                uint32_t ad = sA + swz((uint32_t)(row << 7) + (ch << 4));
                LDSM4(a[mt][0], a[mt][1], a[mt][2], a[mt][3], ad);
            }
#pragma unroll
            for (int bp = 0; bp < NT / 2; bp++) {
                int row = n0w + bp * 16 + (lane & 7) + ((lane & 16) >> 1);
                int ch = ks * 2 + ((lane & 8) >> 3);
                uint32_t ad = sB + swz((uint32_t)(row << 7) + (ch << 4));
                LDSM4(bfr[bp][0], bfr[bp][1], bfr[bp][2], bfr[bp][3], ad);
            }
#pragma unroll
            for (int mt = 0; mt < MT; mt++)
#pragma unroll
                for (int nt = 0; nt < NT; nt++)
                    MMA16816(acc[mt][nt], a[mt],
                             bfr[nt >> 1][(nt & 1) * 2], bfr[nt >> 1][(nt & 1) * 2 + 1]);
        }
    }

#pragma unroll
    for (int mt = 0; mt < MT; mt++) {
        int r0 = bm + m0w + mt * 16 + (lane >> 2);
        int r1 = r0 + 8;
#pragma unroll
        for (int nt = 0; nt < NT; nt++) {
            int col = bn + n0w + nt * 8 + ((lane & 3) << 1);
            float bv0 = bias[col], bv1 = bias[col + 1];
            float v0 = acc[mt][nt][0] + bv0, v1 = acc[mt][nt][1] + bv1;
            float v2 = acc[mt][nt][2] + bv0, v3 = acc[mt][nt][3] + bv1;
            if (mode & 1) {
                v0 = gelu_exact(v0); v1 = gelu_exact(v1);
                v2 = gelu_exact(v2); v3 = gelu_exact(v3);
            }
            if (r0 < M) {
                if (mode & 2) *(float2*)(out + (size_t)r0 * N + col) = make_float2(v0, v1);
                if (mode & 4) aug_store(outAug, (size_t)r0 * 3 * N, N, col, v0, v1);
            }
            if (r1 < M) {
                if (mode & 2) *(float2*)(out + (size_t)r1 * N + col) = make_float2(v2, v3);
                if (mode & 4) aug_store(outAug, (size_t)r1 * 3 * N, N, col, v2, v3);
            }
        }
    }
}

// ==================== batched aug GEMM for attention pieces ====================
// out[bz][MA rows][cols] = A[bz][MA][K3] . B[bz][NB][K3]^T
// epi 0: o = sigmoid(acc*SCALE) fp32 [bz][196][196]
// epi 1: cA aug, row b*196+m, col h*96+d  (bz = b*8+h)
__global__ __launch_bounds__(256) void gemm_bat(
    const bf16* __restrict__ Aall, const bf16* __restrict__ Ball,
    float* __restrict__ oOut, uint16_t* __restrict__ cAug,
    int MA, int NB, int K3, int epi)
{
    constexpr int BM = 128, BN = 128, MT = 4, NT = 4;
    constexpr int A_BYTES = BM * 128;
    constexpr int STG = (BM + BN) * 128;
    extern __shared__ __align__(1024) char smem[];
    uint32_t sb = smem_u32(smem);
    int tid = threadIdx.x, wid = tid >> 5, lane = tid & 31;
    int bz = blockIdx.z;
    const bf16* A = Aall + (size_t)bz * MA * K3;
    const bf16* Bw = Ball + (size_t)bz * NB * K3;
    int bm = blockIdx.y * BM, bn = blockIdx.x * BN;
    int m0w = (wid & 1) * 64;
    int n0w = (wid >> 1) * 32;
    int NC = K3 >> 6;

    auto load_stage = [&](int c) {
        uint32_t stage = sb + (c % GS) * STG;
        int k0 = c << 6;
#pragma unroll
        for (int g0 = 0; g0 < (BM + BN) * 8; g0 += 256) {
            int g = g0 + tid;
            int isB = (g >= BM * 8);
            int q = isB ? (g - BM * 8) : g;
            int row = q >> 3, c16 = q & 7;
            uint32_t dst = stage + (isB ? A_BYTES : 0) + swz((row << 7) + (c16 << 4));
            const bf16* src;
            int pred;
            if (!isB) {
                int gr = bm + row; pred = gr < MA;
                src = A + (size_t)(pred ? gr : 0) * K3 + k0 + (c16 << 3);
            } else {
                int gr = bn + row; pred = gr < NB;
                src = Bw + (size_t)(pred ? gr : 0) * K3 + k0 + (c16 << 3);
            }
            cp16(dst, src, pred);
        }
        asm volatile("cp.async.commit_group;" ::: "memory");
    };

    float acc[MT][NT][4];
#pragma unroll
    for (int mt = 0; mt < MT; mt++)
#pragma unroll
        for (int nt = 0; nt < NT; nt++)
#pragma unroll
            for (int i = 0; i < 4; i++) acc[mt][nt][i] = 0.f;

    load_stage(0);
    load_stage(1);

    for (int c = 0; c < NC; c++) {
        if (c == NC - 1) asm volatile("cp.async.wait_group 0;" ::: "memory");
        else             asm volatile("cp.async.wait_group 1;" ::: "memory");
        __syncthreads();
        if (c + 2 < NC) load_stage(c + 2);

        uint32_t sA = sb + (c % GS) * STG;
        uint32_t sB = sA + A_BYTES;
#pragma unroll
        for (int ks = 0; ks < 4; ks++) {
            uint32_t a[MT][4], bfr[NT / 2][4];
#pragma unroll
            for (int mt = 0; mt < MT; mt++) {
                int row = m0w + mt * 16 + (lane & 15);
                int ch = ks * 2 + (lane >> 4);
                uint32_t ad = sA + swz((uint32_t)(row << 7) + (ch << 4));
                LDSM4(a[mt][0], a[mt][1], a[mt][2], a[mt][3], ad);
            }
#pragma unroll
            for (int bp = 0; bp < NT / 2; bp++) {
                int row = n0w + bp * 16 + (lane & 7) + ((lane & 16) >> 1);
                int ch = ks * 2 + ((lane & 8) >> 3);
                uint32_t ad = sB + swz((uint32_t)(row << 7) + (ch << 4));
                LDSM4(bfr[bp][0], bfr[bp][1], bfr[bp][2], bfr[bp][3], ad);
            }
#pragma unroll
            for (int mt = 0; mt < MT; mt++)
#pragma unroll
                for (int nt = 0; nt < NT; nt++)
                    MMA16816(acc[mt][nt], a[mt],
                             bfr[nt >> 1][(nt & 1) * 2], bfr[nt >> 1][(nt & 1) * 2 + 1]);
        }
    }

    int bb = bz >> 3, hh = bz & 7;
#pragma unroll
    for (int mt = 0; mt < MT; mt++) {
        int r0 = bm + m0w + mt * 16 + (lane >> 2);
        int r1 = r0 + 8;
#pragma unroll
        for (int nt = 0; nt < NT; nt++) {
            int col = bn + n0w + nt * 8 + ((lane & 3) << 1);
            float v0 = acc[mt][nt][0], v1 = acc[mt][nt][1];
            float v2 = acc[mt][nt][2], v3 = acc[mt][nt][3];
            if (epi == 0) {
                if (col + 1 < 196) {
                    if (r0 < 196) {
                        float2 w = make_float2(1.f/(1.f+expf(-v0*SCALE_)),
                                               1.f/(1.f+expf(-v1*SCALE_)));
                        *(float2*)(oOut + ((size_t)bz*196 + r0)*196 + col) = w;
                    }
                    if (r1 < 196) {
                        float2 w = make_float2(1.f/(1.f+expf(-v2*SCALE_)),
                                               1.f/(1.f+expf(-v3*SCALE_)));
                        *(float2*)(oOut + ((size_t)bz*196 + r1)*196 + col) = w;
                    }
                }
            } else {
                if (col + 1 < 96) {
                    if (r0 < 196)
                        aug_store(cAug, (size_t)(bb*196 + r0) * 3 * C_, C_, hh*96 + col, v0, v1);
                    if (r1 < 196)
                        aug_store(cAug, (size_t)(bb*196 + r1) * 3 * C_, C_, hh*96 + col, v2, v3);
                }
            }
        }
    }
}

// W [K][N] fp32 -> aug bf16 [N][3K] = [hi|lo|hi]
__global__ void wsplitT(const float* __restrict__ w, uint16_t* __restrict__ aug,
                        int K, int N)
{
    __shared__ float t[32][33];
    int n0 = blockIdx.x * 32, k0 = blockIdx.y * 32;
    int tx = threadIdx.x, ty = threadIdx.y;
#pragma unroll
    for (int j = 0; j < 4; j++)
        t[ty + 8 * j][tx] = w[(size_t)(k0 + ty + 8 * j) * N + n0 + tx];
    __syncthreads();
#pragma unroll
    for (int j = 0; j < 4; j++) {
        float v = t[tx][ty + 8 * j];
        int n = n0 + ty + 8 * j, k = k0 + tx;
        bf16 h = __float2bfloat16(v);
        bf16 l = __float2bfloat16(v - __bfloat162float(h));
        size_t base = (size_t)n * 3 * K;
        *(bf16*)(aug + base + k)         = h;
        *(bf16*)(aug + base + K + k)     = l;
        *(bf16*)(aug + base + 2 * K + k) = h;
    }
}

// ==================== pack kernels for attention ====================
// q/k fp32 [1568][768] -> [bh][n][384] per-head aug (zero-padded d 96..127)
// isK=0: hi|hi|lo ; isK=1: hi|lo|hi
__global__ void pack_qk(const float* __restrict__ src, uint16_t* __restrict__ dst, int isK)
{
    int idx = blockIdx.x * 256 + threadIdx.x;   // u32 slots
    if (idx >= 64 * 196 * 192) return;
    int c = idx % 192, row = idx / 192;
    int bh = row / 196, n = row % 196;
    int b = bh >> 3, h = bh & 7;
    int s = c >> 6, d = (c & 63) * 2;
    uint32_t val = 0;
    if (d < 96) {
        float2 v = *(const float2*)(src + ((size_t)b*196 + n)*768 + h*96 + d);
        bf16 h0 = __float2bfloat16(v.x), h1 = __float2bfloat16(v.y);
        int isLo = isK ? (s == 1) : (s == 2);
        __nv_bfloat162 pk;
        if (isLo)
            pk = __halves2bfloat162(__float2bfloat16(v.x - __bfloat162float(h0)),
                                    __float2bfloat16(v.y - __bfloat162float(h1)));
        else
            pk = __halves2bfloat162(h0, h1);
        val = *(uint32_t*)&pk;
    }
    ((uint32_t*)dst)[(size_t)row * 192 + c] = val;
}

// o [bh][n][m] -> oT3 [bh][m][s*256+n], slices hi|hi|lo, n padded to 256 w/ zeros
__global__ void pack_oT(const float* __restrict__ o, uint16_t* __restrict__ dst)
{
    __shared__ float t[32][33];
    int bh = blockIdx.z, m0 = blockIdx.x * 32, n0 = blockIdx.y * 32;
    int tx = threadIdx.x, ty = threadIdx.y;
#pragma unroll
    for (int j = 0; j < 4; j++) {
        int n = n0 + ty + 8 * j, m = m0 + tx;
        t[ty + 8 * j][tx] = (n < 196 && m < 196) ? o[((size_t)bh*196 + n)*196 + m] : 0.f;
    }
    __syncthreads();
#pragma unroll
    for (int j = 0; j < 4; j++) {
        int m = m0 + ty + 8 * j, n = n0 + tx;
        if (m < 196) {
            float v = t[tx][ty + 8 * j];
            bf16 h = __float2bfloat16(v);
            bf16 l = __float2bfloat16(v - __bfloat162float(h));
            size_t base = ((size_t)bh*196 + m) * 768;
            dst[base + n]       = *(uint16_t*)&h;
            dst[base + 256 + n] = *(uint16_t*)&h;
            dst[base + 512 + n] = *(uint16_t*)&l;
        }
    }
}

// cg [b][n][768] -> cgT3 [bh][d][s*256+n], slices hi|lo|hi
__global__ void pack_cgT(const float* __restrict__ cg, uint16_t* __restrict__ dst)
{
    __shared__ float t[32][33];
    int bh = blockIdx.z, d0 = blockIdx.x * 32, n0 = blockIdx.y * 32;
    int b = bh >> 3, h = bh & 7;
    int tx = threadIdx.x, ty = threadIdx.y;
#pragma unroll
    for (int j = 0; j < 4; j++) {
        int n = n0 + ty + 8 * j;
        t[ty + 8 * j][tx] = (n < 196) ? cg[((size_t)b*196 + n)*768 + h*96 + d0 + tx] : 0.f;
    }
    __syncthreads();
#pragma unroll
    for (int j = 0; j < 4; j++) {
        int d = d0 + ty + 8 * j, n = n0 + tx;
        float v = t[tx][ty + 8 * j];
        bf16 hv = __float2bfloat16(v);
        bf16 lv = __float2bfloat16(v - __bfloat162float(hv));
        size_t base = ((size_t)bh*96 + d) * 768;
        dst[base + n]       = *(uint16_t*)&hv;
        dst[base + 256 + n] = *(uint16_t*)&lv;
        dst[base + 512 + n] = *(uint16_t*)&hv;
    }
}

// ==================== elementwise kernels ====================
__global__ __launch_bounds__(256) void ln_kernel(
    const float* __restrict__ x, const float* __restrict__ w,
    const float* __restrict__ b, float* __restrict__ y)
{
    int row = blockIdx.x;
    const float* xr = x + (size_t)row * C_;
    float v[3], s = 0.f, s2 = 0.f;
#pragma unroll
    for (int i = 0; i < 3; i++) { v[i] = xr[threadIdx.x + i*256]; s += v[i]; s2 += v[i]*v[i]; }
    __shared__ float red[18];
#pragma unroll
    for (int off = 16; off; off >>= 1) {
        s  += __shfl_down_sync(0xffffffffu, s, off);
        s2 += __shfl_down_sync(0xffffffffu, s2, off);
    }
    int wid = threadIdx.x >> 5, lane = threadIdx.x & 31;
    if (lane == 0) { red[wid] = s; red[8+wid] = s2; }
    __syncthreads();
    if (threadIdx.x == 0) {
        float ts = 0.f, ts2 = 0.f;
        for (int i = 0; i < 8; i++) { ts += red[i]; ts2 += red[8+i]; }
        red[16] = ts; red[17] = ts2;
    }
    __syncthreads();
    float mean = red[16] * (1.0f/C_);
    float inv  = rsqrtf(red[17] * (1.0f/C_) - mean*mean + 1e-5f);
    float* yr = y + (size_t)row * C_;
#pragma unroll
    for (int i = 0; i < 3; i++) {
        int c = threadIdx.x + i*256;
        yr[c] = (v[i] - mean) * inv * w[c] + b[c];
    }
}

__global__ __launch_bounds__(256) void final_kernel(
    const float* __restrict__ c2, const float* __restrict__ gate,
    const float* __restrict__ memh, const float* __restrict__ w,
    const float* __restrict__ bb, float* __restrict__ y, uint16_t* __restrict__ aug)
{
    int row = blockIdx.x;
    int b = row / MEM_, m = row % MEM_;
    float v[3], s = 0.f, s2 = 0.f;
#pragma unroll
    for (int i = 0; i < 3; i++) {
        int c = threadIdx.x + i*256;
        float g = gate[(b*H_ + (c/D_))*MEM_ + m];
        v[i] = c2[(size_t)row*C_ + c] + g * memh[(size_t)row*C_ + c];
        s += v[i]; s2 += v[i]*v[i];
    }
    __shared__ float red[18];
#pragma unroll
    for (int off = 16; off; off >>= 1) {
        s  += __shfl_down_sync(0xffffffffu, s, off);
        s2 += __shfl_down_sync(0xffffffffu, s2, off);
    }
    int wid = threadIdx.x >> 5, lane = threadIdx.x & 31;
    if (lane == 0) { red[wid] = s; red[8+wid] = s2; }
    __syncthreads();
    if (threadIdx.x == 0) {
        float ts = 0.f, ts2 = 0.f;
        for (int i = 0; i < 8; i++) { ts += red[i]; ts2 += red[8+i]; }
        red[16] = ts; red[17] = ts2;
    }
    __syncthreads();
    float mean = red[16] * (1.0f/C_);
    float inv  = rsqrtf(red[17] * (1.0f/C_) - mean*mean + 1e-5f);
    float* yr = y + (size_t)row * C_;
    size_t base = (size_t)row * 3 * C_;
#pragma unroll
    for (int i = 0; i < 3; i++) {
        int c = threadIdx.x + i*256;
        float o = (v[i] - mean) * inv * w[c] + bb[c];
        yr[c] = o;
        bf16 h = __float2bfloat16(o);
        aug[base + c]        = *(uint16_t*)&h;
        aug[base + C_ + c]   = *(uint16_t*)&h;
        bf16 l = __float2bfloat16(o - __bfloat162float(h));
        aug[base + 2*C_ + c] = *(uint16_t*)&l;
    }
}

__global__ void initmem_kernel(const float* __restrict__ x, float* __restrict__ mem,
                               uint16_t* __restrict__ aug)
{
    int idx = blockIdx.x * 256 + threadIdx.x;
    if (idx >= B_*MEM_*C_/2) return;
    int row = idx / (C_/2), jp = (idx % (C_/2)) * 2;
    int b = row / MEM_, r = row % MEM_;
    float2 v = *(const float2*)(x + (size_t)b*T_*N_*C_ + (size_t)r*C_ + jp);
    *(float2*)(mem + (size_t)row*C_ + jp) = v;
    aug_store(aug, (size_t)row * 3 * C_, C_, jp, v.x, v.y);
}

__global__ void ap_kernel(const float* __restrict__ mem, float* __restrict__ ap)
{
    int idx = blockIdx.x * 256 + threadIdx.x;
    if (idx >= B_*C_) return;
    int b = idx / C_, c = idx % C_;
    float s = 0.f;
    const float* p = mem + (size_t)b*MEM_*C_ + c;
    for (int m = 0; m < MEM_; m++) s += p[(size_t)m*C_];
    ap[idx] = s * (1.0f/MEM_);
}

__global__ void cat_aug_kernel(const float* __restrict__ x, const float* __restrict__ ap,
                               uint16_t* __restrict__ aug, int t)
{
    int idx = blockIdx.x * 256 + threadIdx.x;
    if (idx >= ROWS_ * 768) return;
    int row = idx / 768, jp = (idx % 768) * 2;
    int b = row / N_, n = row % N_;
    float2 v;
    if (jp < C_) v = *(const float2*)(x + (((size_t)b*T_ + t)*N_ + n)*C_ + jp);
    else         v = *(const float2*)(ap + b*C_ + jp - C_);
    aug_store(aug, (size_t)row * 3 * (2*C_), 2*C_, jp, v.x, v.y);
}

__global__ void gate_kernel(const float* __restrict__ o, float* __restrict__ gate)
{
    int idx = blockIdx.x * 256 + threadIdx.x;
    if (idx >= B_*H_*MEM_) return;
    int m = idx % MEM_, bh = idx / MEM_;
    const float* op = o + (size_t)bh*N_*MEM_ + m;
    float s = 0.f;
    for (int n = 0; n < N_; n++) s += op[(size_t)n*MEM_];
    gate[idx] = 1.0f - s * (1.0f/N_);
}

// ==================== host orchestration ====================
#define SMEM_BIG (GS * (128 + 256) * 128)   // 147456
#define SMEM_SM  (GS * (64 + 128) * 128)    // 73728
#define SMEM_BAT (GS * (128 + 128) * 128)   // 98304

static void gemm_big(const uint16_t* a, const uint16_t* w, const float* bias,
                     float* out, uint16_t* outAug, int M, int N, int K, int mode)
{
    dim3 g(N / 256, (M + 127) / 128);
    gemm_mma<128, 256, 4, 8><<<g, 256, SMEM_BIG>>>(
        (const bf16*)a, (const bf16*)w, bias, out, outAug, M, N, 3 * K, mode);
}
static void gemm_sm(const uint16_t* a, const uint16_t* w, const float* bias,
                    float* out, uint16_t* outAug, int M, int N, int K, int mode)
{
    dim3 g(N / 128, (M + 63) / 64);
    gemm_mma<64, 128, 2, 4><<<g, 256, SMEM_SM>>>(
        (const bf16*)a, (const bf16*)w, bias, out, outAug, M, N, 3 * K, mode);
}

extern "C" void kernel_launch(void* const* d_in, const int* in_sizes, int n_in,
                              void* d_out, int out_size)
{
    const float* cur_fea = (const float*)d_in[0];
    const float* n1w = (const float*)d_in[1];
    const float* n1b = (const float*)d_in[2];
    const float* n2w = (const float*)d_in[3];
    const float* n2b = (const float*)d_in[4];
    const float* c_w1 = (const float*)d_in[5];  const float* c_b1 = (const float*)d_in[6];
    const float* c_w2 = (const float*)d_in[7];  const float* c_b2 = (const float*)d_in[8];
    const float* m_w1 = (const float*)d_in[9];  const float* m_b1 = (const float*)d_in[10];
    const float* m_w2 = (const float*)d_in[11]; const float* m_b2 = (const float*)d_in[12];
    const float* p_w1 = (const float*)d_in[13]; const float* p_b1 = (const float*)d_in[14];
    const float* p_w2 = (const float*)d_in[15]; const float* p_b2 = (const float*)d_in[16];
    const float* q_w = (const float*)d_in[17];  const float* q_b = (const float*)d_in[18];
    const float* k_w = (const float*)d_in[19];  const float* k_b = (const float*)d_in[20];

    cudaFuncSetAttribute((const void*)gemm_mma<128, 256, 4, 8>,
                         cudaFuncAttributeMaxDynamicSharedMemorySize, SMEM_BIG);
    cudaFuncSetAttribute((const void*)gemm_mma<64, 128, 2, 4>,
                         cudaFuncAttributeMaxDynamicSharedMemorySize, SMEM_SM);
    cudaFuncSetAttribute((const void*)gemm_bat,
                         cudaFuncAttributeMaxDynamicSharedMemorySize, SMEM_BAT);

    float *x, *cg, *memh, *qb, *kb, *o, *c2, *gate, *ap, *memA, *memB;
    cudaGetSymbolAddress((void**)&x, g_x);       cudaGetSymbolAddress((void**)&cg, g_cg);
    cudaGetSymbolAddress((void**)&memh, g_memh); cudaGetSymbolAddress((void**)&qb, g_q);
    cudaGetSymbolAddress((void**)&kb, g_kk);     cudaGetSymbolAddress((void**)&o, g_o);
    cudaGetSymbolAddress((void**)&c2, g_c2);     cudaGetSymbolAddress((void**)&gate, g_gate);
    cudaGetSymbolAddress((void**)&ap, g_ap);
    cudaGetSymbolAddress((void**)&memA, g_memA); cudaGetSymbolAddress((void**)&memB, g_memB);

    uint16_t *hidA, *catA, *cgA, *cA, *memAg, *Q3, *K3, *oT3, *cgT3;
    uint16_t *wc1, *wc2, *wm1, *wm2, *wp1, *wp2, *wq, *wk;
    cudaGetSymbolAddress((void**)&hidA, g_hidA); cudaGetSymbolAddress((void**)&catA, g_catA);
    cudaGetSymbolAddress((void**)&cgA, g_cgA);   cudaGetSymbolAddress((void**)&cA, g_cA);
    cudaGetSymbolAddress((void**)&memAg, g_memAg);
    cudaGetSymbolAddress((void**)&Q3, g_Q3);     cudaGetSymbolAddress((void**)&K3, g_K3);
    cudaGetSymbolAddress((void**)&oT3, g_oT3);   cudaGetSymbolAddress((void**)&cgT3, g_cgT3);
    cudaGetSymbolAddress((void**)&wc1, g_wc1);   cudaGetSymbolAddress((void**)&wc2, g_wc2);
    cudaGetSymbolAddress((void**)&wm1, g_wm1);   cudaGetSymbolAddress((void**)&wm2, g_wm2);
    cudaGetSymbolAddress((void**)&wp1, g_wp1);   cudaGetSymbolAddress((void**)&wp2, g_wp2);
    cudaGetSymbolAddress((void**)&wq, g_wq);     cudaGetSymbolAddress((void**)&wk, g_wk);

    dim3 wb(32, 8);
    wsplitT<<<dim3(HID_/32, (2*C_)/32), wb>>>(c_w1, wc1, 2*C_, HID_);
    wsplitT<<<dim3(C_/32, HID_/32),    wb>>>(c_w2, wc2, HID_, C_);
    wsplitT<<<dim3(HID_/32, C_/32),    wb>>>(m_w1, wm1, C_, HID_);
    wsplitT<<<dim3(C_/32, HID_/32),    wb>>>(m_w2, wm2, HID_, C_);
    wsplitT<<<dim3(HID_/32, C_/32),    wb>>>(p_w1, wp1, C_, HID_);
    wsplitT<<<dim3(C_/32, HID_/32),    wb>>>(p_w2, wp2, HID_, C_);
    wsplitT<<<dim3(C_/32, C_/32),      wb>>>(q_w, wq, C_, C_);
    wsplitT<<<dim3(C_/32, C_/32),      wb>>>(k_w, wk, C_, C_);

    ln_kernel<<<B_*T_*N_, 256>>>(cur_fea, n1w, n1b, x);
    initmem_kernel<<<(B_*MEM_*C_/2 + 255)/256, 256>>>(x, memA, memAg);

    float* mcur = memA;
    float* mnxt = memB;

    for (int t = 1; t < T_; t++) {
        ap_kernel<<<(B_*C_ + 255)/256, 256>>>(mcur, ap);
        cat_aug_kernel<<<(ROWS_*768 + 255)/256, 256>>>(x, ap, catA, t);

        gemm_big(catA, wc1, c_b1, nullptr, hidA, ROWS_, HID_, 2*C_, 1|4);  // fc1_c
        gemm_sm (hidA, wc2, c_b2, cg, cgA, ROWS_, C_, HID_, 2|4);          // fc2_c
        gemm_big(memAg, wm1, m_b1, nullptr, hidA, ROWS_, HID_, C_, 1|4);   // fc1_m
        gemm_sm (hidA, wm2, m_b2, memh, nullptr, ROWS_, C_, HID_, 2);      // fc2_m
        gemm_sm (memAg, wk, k_b, kb, nullptr, ROWS_, C_, C_, 2);           // k
        gemm_sm (cgA, wq, q_b, qb, nullptr, ROWS_, C_, C_, 2);             // q

        pack_qk<<<(64*196*192 + 255)/256, 256>>>(qb, Q3, 0);
        pack_qk<<<(64*196*192 + 255)/256, 256>>>(kb, K3, 1);
        // attn: o[bh][n][m] = sigmoid(Q3 . K3^T * scale)
        gemm_bat<<<dim3(2, 2, 64), 256, SMEM_BAT>>>(
            (const bf16*)Q3, (const bf16*)K3, o, nullptr, 196, 196, 384, 0);
        gate_kernel<<<(B_*H_*MEM_ + 255)/256, 256>>>(o, gate);
        pack_oT<<<dim3(7, 8, 64), wb>>>(o, oT3);
        pack_cgT<<<dim3(3, 8, 64), wb>>>(cg, cgT3);
        // cgather: cA[b*196+m][h*96+d] = oT3 . cgT3^T (aug out)
        gemm_bat<<<dim3(1, 2, 64), 256, SMEM_BAT>>>(
            (const bf16*)oT3, (const bf16*)cgT3, nullptr, cA, 196, 96, 768, 1);

        gemm_big(cA, wp1, p_b1, nullptr, hidA, ROWS_, HID_, C_, 1|4);      // fc1_p
        gemm_sm (hidA, wp2, p_b2, c2, nullptr, ROWS_, C_, HID_, 2);        // fc2_p

        float* dst = (t == T_ - 1) ? (float*)d_out : mnxt;
        final_kernel<<<B_*MEM_, 256>>>(c2, gate, memh, n2w, n2b, dst, memAg);

        float* tmp = mcur; mcur = mnxt; mnxt = tmp;
    }
}

// round 7
// speedup vs baseline: 2.3271x; 1.0823x over previous
#include <cuda_runtime.h>
#include <cuda_bf16.h>
#include <math.h>
#include <stdint.h>

#define B_   8
#define T_   16
#define N_   196
#define C_   768
#define H_   8
#define D_   96
#define MEM_ 196
#define HID_ 3072
#define ROWS_ 1568
#define SCALE_ 0.1020620726159657f

typedef __nv_bfloat16 bf16;

// ---------------- fp32 scratch ----------------
__device__ __align__(256) float g_x   [B_*T_*N_*C_];
__device__ __align__(256) float g_cg  [ROWS_*C_];
__device__ __align__(256) float g_memh[ROWS_*C_];
__device__ __align__(256) float g_q   [ROWS_*C_];
__device__ __align__(256) float g_kk  [ROWS_*C_];
__device__ __align__(256) float g_o   [B_*H_*N_*MEM_];
__device__ __align__(256) float g_c2  [ROWS_*C_];
__device__ __align__(256) float g_gate[B_*H_*MEM_];
__device__ __align__(256) float g_ap  [B_*C_];
__device__ __align__(256) float g_bias2[B_*HID_];
__device__ __align__(256) float g_memA[ROWS_*C_];
__device__ __align__(256) float g_memB[ROWS_*C_];

// ---------------- augmented bf16 activations ----------------
__device__ __align__(256) uint16_t g_xA  [T_*B_*N_*3*C_];   // [t][b][n][hi|hi|lo] (115MB)
__device__ __align__(256) uint16_t g_hidA[ROWS_*3*HID_];
__device__ __align__(256) uint16_t g_cgA [ROWS_*3*C_];
__device__ __align__(256) uint16_t g_cA  [ROWS_*3*C_];
__device__ __align__(256) uint16_t g_memAg[ROWS_*3*C_];

// attention aug operands
__device__ __align__(256) uint16_t g_Q3 [64*196*384];
__device__ __align__(256) uint16_t g_K3 [64*196*384];
__device__ __align__(256) uint16_t g_oT3[64*196*768];
__device__ __align__(256) uint16_t g_cgT3[64*96*768];

// weights augmented [N][3K] = [hi|lo|hi]
__device__ __align__(256) uint16_t g_wc1[HID_*3*C_];     // top 768 rows of c_w1 only
__device__ __align__(256) uint16_t g_wc2[C_*3*HID_];
__device__ __align__(256) uint16_t g_wm1[HID_*3*C_];
__device__ __align__(256) uint16_t g_wm2[C_*3*HID_];
__device__ __align__(256) uint16_t g_wp1[HID_*3*C_];
__device__ __align__(256) uint16_t g_wp2[C_*3*HID_];
__device__ __align__(256) uint16_t g_wq [C_*3*C_];
__device__ __align__(256) uint16_t g_wk [C_*3*C_];

__device__ __forceinline__ float gelu_exact(float x) {
    return 0.5f * x * (1.0f + erff(x * 0.70710678118654752f));
}
__device__ __forceinline__ uint32_t smem_u32(const void* p) {
    uint32_t a;
    asm("{ .reg .u64 t; cvta.to.shared.u64 t, %1; cvt.u32.u64 %0, t; }" : "=r"(a) : "l"(p));
    return a;
}
__device__ __forceinline__ void cp16(uint32_t dst, const void* src, int pred) {
    int sz = pred ? 16 : 0;
    asm volatile("cp.async.cg.shared.global [%0], [%1], 16, %2;" :: "r"(dst), "l"(src), "r"(sz) : "memory");
}
__device__ __forceinline__ uint32_t swz(uint32_t o) { return o ^ ((o >> 3) & 0x70); }

#define LDSM4(r0, r1, r2, r3, addr) \
    asm volatile("ldmatrix.sync.aligned.m8n8.x4.shared.b16 {%0,%1,%2,%3}, [%4];" \
        : "=r"(r0), "=r"(r1), "=r"(r2), "=r"(r3) : "r"(addr))

#define MMA16816(d, a, b0, b1) \
    asm volatile("mma.sync.aligned.m16n8k16.row.col.f32.bf16.bf16.f32 " \
        "{%0,%1,%2,%3}, {%4,%5,%6,%7}, {%8,%9}, {%0,%1,%2,%3};" \
        : "+f"((d)[0]), "+f"((d)[1]), "+f"((d)[2]), "+f"((d)[3]) \
        : "r"((a)[0]), "r"((a)[1]), "r"((a)[2]), "r"((a)[3]), "r"(b0), "r"(b1))

__device__ __forceinline__ void aug_store(uint16_t* aug, size_t base, int Ncols, int col,
                                          float v0, float v1)
{
    bf16 h0 = __float2bfloat16(v0), h1 = __float2bfloat16(v1);
    __nv_bfloat162 hh = __halves2bfloat162(h0, h1);
    __nv_bfloat162 ll = __halves2bfloat162(__float2bfloat16(v0 - __bfloat162float(h0)),
                                           __float2bfloat16(v1 - __bfloat162float(h1)));
    *(uint32_t*)(aug + base + col)             = *(uint32_t*)&hh;
    *(uint32_t*)(aug + base + Ncols + col)     = *(uint32_t*)&hh;
    *(uint32_t*)(aug + base + 2 * Ncols + col) = *(uint32_t*)&ll;
}

// ==================== weight-vs-activation GEMM ====================
// mode bits: 1=gelu, 2=write fp32 out, 4=write aug, 8=per-batch bias (row/196)
#define GS 3

template<int BM, int BN, int MT, int NT>
__global__ __launch_bounds__(256) void gemm_mma(
    const bf16* __restrict__ A, const bf16* __restrict__ Bw,
    const float* __restrict__ bias, float* __restrict__ out,
    uint16_t* __restrict__ outAug, int M, int N, int K3, int mode)
{
    constexpr int A_BYTES = BM * 128;
    constexpr int STG = (BM + BN) * 128;
    extern __shared__ __align__(1024) char smem[];
    uint32_t sb = smem_u32(smem);
    int tid = threadIdx.x, wid = tid >> 5, lane = tid & 31;
    int bm = blockIdx.y * BM, bn = blockIdx.x * BN;
    int m0w = (wid & 1) * (MT * 16);
    int n0w = (wid >> 1) * (NT * 8);
    int NC = K3 >> 6;

    auto load_stage = [&](int c) {
        uint32_t stage = sb + (c % GS) * STG;
        int k0 = c << 6;
        constexpr int TOT = (BM + BN) * 8;
#pragma unroll
        for (int g0 = 0; g0 < TOT; g0 += 256) {
            int g = g0 + tid;
            int isB = (g >= BM * 8);
            int q = isB ? (g - BM * 8) : g;
            int row = q >> 3, c16 = q & 7;
            uint32_t dst = stage + (isB ? A_BYTES : 0) + swz((row << 7) + (c16 << 4));
            const bf16* src;
            int pred = 1;
            if (!isB) {
                int gr = bm + row; pred = gr < M;
                src = A + (size_t)(pred ? gr : 0) * K3 + k0 + (c16 << 3);
            } else {
                int gr = bn + row;
                src = Bw + (size_t)gr * K3 + k0 + (c16 << 3);
            }
            cp16(dst, src, pred);
        }
        asm volatile("cp.async.commit_group;" ::: "memory");
    };

    float acc[MT][NT][4];
#pragma unroll
    for (int mt = 0; mt < MT; mt++)
#pragma unroll
        for (int nt = 0; nt < NT; nt++)
#pragma unroll
            for (int i = 0; i < 4; i++) acc[mt][nt][i] = 0.f;

    load_stage(0);
    load_stage(1);

    for (int c = 0; c < NC; c++) {
        if (c == NC - 1) asm volatile("cp.async.wait_group 0;" ::: "memory");
        else             asm volatile("cp.async.wait_group 1;" ::: "memory");
        __syncthreads();
        if (c + 2 < NC) load_stage(c + 2);

        uint32_t sA = sb + (c % GS) * STG;
        uint32_t sB = sA + A_BYTES;
#pragma unroll
        for (int ks = 0; ks < 4; ks++) {
            uint32_t a[MT][4], bfr[NT / 2][4];
#pragma unroll
            for (int mt = 0; mt < MT; mt++) {
                int row = m0w + mt * 16 + (lane & 15);
                int ch = ks * 2 + (lane >> 4);
                uint32_t ad = sA + swz((uint32_t)(row << 7) + (ch << 4));
                LDSM4(a[mt][0], a[mt][1], a[mt][2], a[mt][3], ad);
            }
#pragma unroll
            for (int bp = 0; bp < NT / 2; bp++) {
                int row = n0w + bp * 16 + (lane & 7) + ((lane & 16) >> 1);
                int ch = ks * 2 + ((lane & 8) >> 3);
                uint32_t ad = sB + swz((uint32_t)(row << 7) + (ch << 4));
                LDSM4(bfr[bp][0], bfr[bp][1], bfr[bp][2], bfr[bp][3], ad);
            }
#pragma unroll
            for (int mt = 0; mt < MT; mt++)
#pragma unroll
                for (int nt = 0; nt < NT; nt++)
                    MMA16816(acc[mt][nt], a[mt],
                             bfr[nt >> 1][(nt & 1) * 2], bfr[nt >> 1][(nt & 1) * 2 + 1]);
        }
    }

#pragma unroll
    for (int mt = 0; mt < MT; mt++) {
        int r0 = bm + m0w + mt * 16 + (lane >> 2);
        int r1 = r0 + 8;
#pragma unroll
        for (int nt = 0; nt < NT; nt++) {
            int col = bn + n0w + nt * 8 + ((lane & 3) << 1);
            if (r0 < M) {
                int bb = (mode & 8) ? (r0 / 196) * N : 0;
                float v0 = acc[mt][nt][0] + bias[bb + col];
                float v1 = acc[mt][nt][1] + bias[bb + col + 1];
                if (mode & 1) { v0 = gelu_exact(v0); v1 = gelu_exact(v1); }
                if (mode & 2) *(float2*)(out + (size_t)r0 * N + col) = make_float2(v0, v1);
                if (mode & 4) aug_store(outAug, (size_t)r0 * 3 * N, N, col, v0, v1);
            }
            if (r1 < M) {
                int bb = (mode & 8) ? (r1 / 196) * N : 0;
                float v2 = acc[mt][nt][2] + bias[bb + col];
                float v3 = acc[mt][nt][3] + bias[bb + col + 1];
                if (mode & 1) { v2 = gelu_exact(v2); v3 = gelu_exact(v3); }
                if (mode & 2) *(float2*)(out + (size_t)r1 * N + col) = make_float2(v2, v3);
                if (mode & 4) aug_store(outAug, (size_t)r1 * 3 * N, N, col, v2, v3);
            }
        }
    }
}

// ==================== batched aug GEMM for attention ====================
__global__ __launch_bounds__(256) void gemm_bat(
    const bf16* __restrict__ Aall, const bf16* __restrict__ Ball,
    float* __restrict__ oOut, uint16_t* __restrict__ cAug,
    int MA, int NB, int K3, int epi)
{
    constexpr int BM = 128, BN = 128, MT = 4, NT = 4;
    constexpr int A_BYTES = BM * 128;
    constexpr int STG = (BM + BN) * 128;
    extern __shared__ __align__(1024) char smem[];
    uint32_t sb = smem_u32(smem);
    int tid = threadIdx.x, wid = tid >> 5, lane = tid & 31;
    int bz = blockIdx.z;
    const bf16* A = Aall + (size_t)bz * MA * K3;
    const bf16* Bw = Ball + (size_t)bz * NB * K3;
    int bm = blockIdx.y * BM, bn = blockIdx.x * BN;
    int m0w = (wid & 1) * 64;
    int n0w = (wid >> 1) * 32;
    int NC = K3 >> 6;

    auto load_stage = [&](int c) {
        uint32_t stage = sb + (c % GS) * STG;
        int k0 = c << 6;
#pragma unroll
        for (int g0 = 0; g0 < (BM + BN) * 8; g0 += 256) {
            int g = g0 + tid;
            int isB = (g >= BM * 8);
            int q = isB ? (g - BM * 8) : g;
            int row = q >> 3, c16 = q & 7;
            uint32_t dst = stage + (isB ? A_BYTES : 0) + swz((row << 7) + (c16 << 4));
            const bf16* src;
            int pred;
            if (!isB) {
                int gr = bm + row; pred = gr < MA;
                src = A + (size_t)(pred ? gr : 0) * K3 + k0 + (c16 << 3);
            } else {
                int gr = bn + row; pred = gr < NB;
                src = Bw + (size_t)(pred ? gr : 0) * K3 + k0 + (c16 << 3);
            }
            cp16(dst, src, pred);
        }
        asm volatile("cp.async.commit_group;" ::: "memory");
    };

    float acc[MT][NT][4];
#pragma unroll
    for (int mt = 0; mt < MT; mt++)
#pragma unroll
        for (int nt = 0; nt < NT; nt++)
#pragma unroll
            for (int i = 0; i < 4; i++) acc[mt][nt][i] = 0.f;

    load_stage(0);
    load_stage(1);

    for (int c = 0; c < NC; c++) {
        if (c == NC - 1) asm volatile("cp.async.wait_group 0;" ::: "memory");
        else             asm volatile("cp.async.wait_group 1;" ::: "memory");
        __syncthreads();
        if (c + 2 < NC) load_stage(c + 2);

        uint32_t sA = sb + (c % GS) * STG;
        uint32_t sB = sA + A_BYTES;
#pragma unroll
        for (int ks = 0; ks < 4; ks++) {
            uint32_t a[MT][4], bfr[NT / 2][4];
#pragma unroll
            for (int mt = 0; mt < MT; mt++) {
                int row = m0w + mt * 16 + (lane & 15);
                int ch = ks * 2 + (lane >> 4);
                uint32_t ad = sA + swz((uint32_t)(row << 7) + (ch << 4));
                LDSM4(a[mt][0], a[mt][1], a[mt][2], a[mt][3], ad);
            }
#pragma unroll
            for (int bp = 0; bp < NT / 2; bp++) {
                int row = n0w + bp * 16 + (lane & 7) + ((lane & 16) >> 1);
                int ch = ks * 2 + ((lane & 8) >> 3);
                uint32_t ad = sB + swz((uint32_t)(row << 7) + (ch << 4));
                LDSM4(bfr[bp][0], bfr[bp][1], bfr[bp][2], bfr[bp][3], ad);
            }
#pragma unroll
            for (int mt = 0; mt < MT; mt++)
#pragma unroll
                for (int nt = 0; nt < NT; nt++)
                    MMA16816(acc[mt][nt], a[mt],
                             bfr[nt >> 1][(nt & 1) * 2], bfr[nt >> 1][(nt & 1) * 2 + 1]);
        }
    }

    int bb = bz >> 3, hh = bz & 7;
#pragma unroll
    for (int mt = 0; mt < MT; mt++) {
        int r0 = bm + m0w + mt * 16 + (lane >> 2);
        int r1 = r0 + 8;
#pragma unroll
        for (int nt = 0; nt < NT; nt++) {
            int col = bn + n0w + nt * 8 + ((lane & 3) << 1);
            float v0 = acc[mt][nt][0], v1 = acc[mt][nt][1];
            float v2 = acc[mt][nt][2], v3 = acc[mt][nt][3];
            if (epi == 0) {
                if (col + 1 < 196) {
                    if (r0 < 196) {
                        float2 w = make_float2(1.f/(1.f+expf(-v0*SCALE_)),
                                               1.f/(1.f+expf(-v1*SCALE_)));
                        *(float2*)(oOut + ((size_t)bz*196 + r0)*196 + col) = w;
                    }
                    if (r1 < 196) {
                        float2 w = make_float2(1.f/(1.f+expf(-v2*SCALE_)),
                                               1.f/(1.f+expf(-v3*SCALE_)));
                        *(float2*)(oOut + ((size_t)bz*196 + r1)*196 + col) = w;
                    }
                }
            } else {
                if (col + 1 < 96) {
                    if (r0 < 196)
                        aug_store(cAug, (size_t)(bb*196 + r0) * 3 * C_, C_, hh*96 + col, v0, v1);
                    if (r1 < 196)
                        aug_store(cAug, (size_t)(bb*196 + r1) * 3 * C_, C_, hh*96 + col, v2, v3);
                }
            }
        }
    }
}

// W [K][N] fp32 -> aug bf16 [N][3K] = [hi|lo|hi] (first K rows of w only)
__global__ void wsplitT(const float* __restrict__ w, uint16_t* __restrict__ aug,
                        int K, int N)
{
    __shared__ float t[32][33];
    int n0 = blockIdx.x * 32, k0 = blockIdx.y * 32;
    int tx = threadIdx.x, ty = threadIdx.y;
#pragma unroll
    for (int j = 0; j < 4; j++)
        t[ty + 8 * j][tx] = w[(size_t)(k0 + ty + 8 * j) * N + n0 + tx];
    __syncthreads();
#pragma unroll
    for (int j = 0; j < 4; j++) {
        float v = t[tx][ty + 8 * j];
        int n = n0 + ty + 8 * j, k = k0 + tx;
        bf16 h = __float2bfloat16(v);
        bf16 l = __float2bfloat16(v - __bfloat162float(h));
        size_t base = (size_t)n * 3 * K;
        *(bf16*)(aug + base + k)         = h;
        *(bf16*)(aug + base + K + k)     = l;
        *(bf16*)(aug + base + 2 * K + k) = h;
    }
}

// ==================== pack kernels for attention ====================
__global__ void pack_qk(const float* __restrict__ src, uint16_t* __restrict__ dst, int isK)
{
    int idx = blockIdx.x * 256 + threadIdx.x;
    if (idx >= 64 * 196 * 192) return;
    int c = idx % 192, row = idx / 192;
    int bh = row / 196, n = row % 196;
    int b = bh >> 3, h = bh & 7;
    int s = c >> 6, d = (c & 63) * 2;
    uint32_t val = 0;
    if (d < 96) {
        float2 v = *(const float2*)(src + ((size_t)b*196 + n)*768 + h*96 + d);
        bf16 h0 = __float2bfloat16(v.x), h1 = __float2bfloat16(v.y);
        int isLo = isK ? (s == 1) : (s == 2);
        __nv_bfloat162 pk;
        if (isLo)
            pk = __halves2bfloat162(__float2bfloat16(v.x - __bfloat162float(h0)),
                                    __float2bfloat16(v.y - __bfloat162float(h1)));
        else
            pk = __halves2bfloat162(h0, h1);
        val = *(uint32_t*)&pk;
    }
    ((uint32_t*)dst)[(size_t)row * 192 + c] = val;
}

__global__ void pack_oT(const float* __restrict__ o, uint16_t* __restrict__ dst)
{
    __shared__ float t[32][33];
    int bh = blockIdx.z, m0 = blockIdx.x * 32, n0 = blockIdx.y * 32;
    int tx = threadIdx.x, ty = threadIdx.y;
#pragma unroll
    for (int j = 0; j < 4; j++) {
        int n = n0 + ty + 8 * j, m = m0 + tx;
        t[ty + 8 * j][tx] = (n < 196 && m < 196) ? o[((size_t)bh*196 + n)*196 + m] : 0.f;
    }
    __syncthreads();
#pragma unroll
    for (int j = 0; j < 4; j++) {
        int m = m0 + ty + 8 * j, n = n0 + tx;
        if (m < 196) {
            float v = t[tx][ty + 8 * j];
            bf16 h = __float2bfloat16(v);
            bf16 l = __float2bfloat16(v - __bfloat162float(h));
            size_t base = ((size_t)bh*196 + m) * 768;
            dst[base + n]       = *(uint16_t*)&h;
            dst[base + 256 + n] = *(uint16_t*)&h;
            dst[base + 512 + n] = *(uint16_t*)&l;
        }
    }
}

__global__ void pack_cgT(const float* __restrict__ cg, uint16_t* __restrict__ dst)
{
    __shared__ float t[32][33];
    int bh = blockIdx.z, d0 = blockIdx.x * 32, n0 = blockIdx.y * 32;
    int b = bh >> 3, h = bh & 7;
    int tx = threadIdx.x, ty = threadIdx.y;
#pragma unroll
    for (int j = 0; j < 4; j++) {
        int n = n0 + ty + 8 * j;
        t[ty + 8 * j][tx] = (n < 196) ? cg[((size_t)b*196 + n)*768 + h*96 + d0 + tx] : 0.f;
    }
    __syncthreads();
#pragma unroll
    for (int j = 0; j < 4; j++) {
        int d = d0 + ty + 8 * j, n = n0 + tx;
        float v = t[tx][ty + 8 * j];
        bf16 hv = __float2bfloat16(v);
        bf16 lv = __float2bfloat16(v - __bfloat162float(hv));
        size_t base = ((size_t)bh*96 + d) * 768;
        dst[base + n]       = *(uint16_t*)&hv;
        dst[base + 256 + n] = *(uint16_t*)&lv;
        dst[base + 512 + n] = *(uint16_t*)&hv;
    }
}

// ==================== elementwise kernels ====================
// LN over full input; also writes xA aug in [t][b][n] layout
__global__ __launch_bounds__(256) void ln_kernel(
    const float* __restrict__ x, const float* __restrict__ w,
    const float* __restrict__ b, float* __restrict__ y, uint16_t* __restrict__ xA)
{
    int row = blockIdx.x;                       // (b*T + t)*N + n
    int bb = row / (T_ * N_);
    int t  = (row / N_) % T_;
    int n  = row % N_;
    size_t xrow = ((size_t)(t * B_ + bb) * N_ + n) * 3 * C_;
    const float* xr = x + (size_t)row * C_;
    float v[3], s = 0.f, s2 = 0.f;
#pragma unroll
    for (int i = 0; i < 3; i++) { v[i] = xr[threadIdx.x + i*256]; s += v[i]; s2 += v[i]*v[i]; }
    __shared__ float red[18];
#pragma unroll
    for (int off = 16; off; off >>= 1) {
        s  += __shfl_down_sync(0xffffffffu, s, off);
        s2 += __shfl_down_sync(0xffffffffu, s2, off);
    }
    int wid = threadIdx.x >> 5, lane = threadIdx.x & 31;
    if (lane == 0) { red[wid] = s; red[8+wid] = s2; }
    __syncthreads();
    if (threadIdx.x == 0) {
        float ts = 0.f, ts2 = 0.f;
        for (int i = 0; i < 8; i++) { ts += red[i]; ts2 += red[8+i]; }
        red[16] = ts; red[17] = ts2;
    }
    __syncthreads();
    float mean = red[16] * (1.0f/C_);
    float inv  = rsqrtf(red[17] * (1.0f/C_) - mean*mean + 1e-5f);
    float* yr = y + (size_t)row * C_;
#pragma unroll
    for (int i = 0; i < 3; i++) {
        int c = threadIdx.x + i*256;
        float o = (v[i] - mean) * inv * w[c] + b[c];
        yr[c] = o;
        bf16 h = __float2bfloat16(o);
        xA[xrow + c]         = *(uint16_t*)&h;
        xA[xrow + C_ + c]    = *(uint16_t*)&h;
        bf16 l = __float2bfloat16(o - __bfloat162float(h));
        xA[xrow + 2*C_ + c]  = *(uint16_t*)&l;
    }
}

// bias2[b][j] = c_b1[j] + sum_k ap[b][k] * c_w1[(768+k)][j]   (fp32)
__global__ __launch_bounds__(256) void apw_kernel(
    const float* __restrict__ ap, const float* __restrict__ c_w1,
    const float* __restrict__ c_b1, float* __restrict__ bias2)
{
    int b = blockIdx.y;
    int j = blockIdx.x * 256 + threadIdx.x;
    __shared__ float aps[768];
    for (int k = threadIdx.x; k < 768; k += 256) aps[k] = ap[b * 768 + k];
    __syncthreads();
    float acc = c_b1[j];
    const float* wp = c_w1 + (size_t)768 * HID_ + j;
#pragma unroll 8
    for (int k = 0; k < 768; k++)
        acc = fmaf(aps[k], wp[(size_t)k * HID_], acc);
    bias2[b * HID_ + j] = acc;
}

__global__ __launch_bounds__(256) void final_kernel(
    const float* __restrict__ c2, const float* __restrict__ gate,
    const float* __restrict__ memh, const float* __restrict__ w,
    const float* __restrict__ bb, float* __restrict__ y, uint16_t* __restrict__ aug)
{
    int row = blockIdx.x;
    int b = row / MEM_, m = row % MEM_;
    float v[3], s = 0.f, s2 = 0.f;
#pragma unroll
    for (int i = 0; i < 3; i++) {
        int c = threadIdx.x + i*256;
        float g = gate[(b*H_ + (c/D_))*MEM_ + m];
        v[i] = c2[(size_t)row*C_ + c] + g * memh[(size_t)row*C_ + c];
        s += v[i]; s2 += v[i]*v[i];
    }
    __shared__ float red[18];
#pragma unroll
    for (int off = 16; off; off >>= 1) {
        s  += __shfl_down_sync(0xffffffffu, s, off);
        s2 += __shfl_down_sync(0xffffffffu, s2, off);
    }
    int wid = threadIdx.x >> 5, lane = threadIdx.x & 31;
    if (lane == 0) { red[wid] = s; red[8+wid] = s2; }
    __syncthreads();
    if (threadIdx.x == 0) {
        float ts = 0.f, ts2 = 0.f;
        for (int i = 0; i < 8; i++) { ts += red[i]; ts2 += red[8+i]; }
        red[16] = ts; red[17] = ts2;
    }
    __syncthreads();
    float mean = red[16] * (1.0f/C_);
    float inv  = rsqrtf(red[17] * (1.0f/C_) - mean*mean + 1e-5f);
    float* yr = y + (size_t)row * C_;
    size_t base = (size_t)row * 3 * C_;
#pragma unroll
    for (int i = 0; i < 3; i++) {
        int c = threadIdx.x + i*256;
        float o = (v[i] - mean) * inv * w[c] + bb[c];
        yr[c] = o;
        bf16 h = __float2bfloat16(o);
        aug[base + c]        = *(uint16_t*)&h;
        aug[base + C_ + c]   = *(uint16_t*)&h;
        bf16 l = __float2bfloat16(o - __bfloat162float(h));
        aug[base + 2*C_ + c] = *(uint16_t*)&l;
    }
}

__global__ void initmem_kernel(const float* __restrict__ x, float* __restrict__ mem,
                               uint16_t* __restrict__ aug)
{
    int idx = blockIdx.x * 256 + threadIdx.x;
    if (idx >= B_*MEM_*C_/2) return;
    int row = idx / (C_/2), jp = (idx % (C_/2)) * 2;
    int b = row / MEM_, r = row % MEM_;
    float2 v = *(const float2*)(x + (size_t)b*T_*N_*C_ + (size_t)r*C_ + jp);
    *(float2*)(mem + (size_t)row*C_ + jp) = v;
    aug_store(aug, (size_t)row * 3 * C_, C_, jp, v.x, v.y);
}

__global__ void ap_kernel(const float* __restrict__ mem, float* __restrict__ ap)
{
    int idx = blockIdx.x * 256 + threadIdx.x;
    if (idx >= B_*C_) return;
    int b = idx / C_, c = idx % C_;
    float s = 0.f;
    const float* p = mem + (size_t)b*MEM_*C_ + c;
    for (int m = 0; m < MEM_; m++) s += p[(size_t)m*C_];
    ap[idx] = s * (1.0f/MEM_);
}

__global__ void gate_kernel(const float* __restrict__ o, float* __restrict__ gate)
{
    int idx = blockIdx.x * 256 + threadIdx.x;
    if (idx >= B_*H_*MEM_) return;
    int m = idx % MEM_, bh = idx / MEM_;
    const float* op = o + (size_t)bh*N_*MEM_ + m;
    float s = 0.f;
    for (int n = 0; n < N_; n++) s += op[(size_t)n*MEM_];
    gate[idx] = 1.0f - s * (1.0f/N_);
}

// ==================== host orchestration ====================
#define SMEM_BIG (GS * (128 + 256) * 128)   // 147456
#define SMEM_SM  (GS * (64 + 128) * 128)    // 73728
#define SMEM_BAT (GS * (128 + 128) * 128)   // 98304

static void gemm_big(const uint16_t* a, const uint16_t* w, const float* bias,
                     float* out, uint16_t* outAug, int M, int N, int K, int mode)
{
    dim3 g(N / 256, (M + 127) / 128);
    gemm_mma<128, 256, 4, 8><<<g, 256, SMEM_BIG>>>(
        (const bf16*)a, (const bf16*)w, bias, out, outAug, M, N, 3 * K, mode);
}
static void gemm_sm(const uint16_t* a, const uint16_t* w, const float* bias,
                    float* out, uint16_t* outAug, int M, int N, int K, int mode)
{
    dim3 g(N / 128, (M + 63) / 64);
    gemm_mma<64, 128, 2, 4><<<g, 256, SMEM_SM>>>(
        (const bf16*)a, (const bf16*)w, bias, out, outAug, M, N, 3 * K, mode);
}

extern "C" void kernel_launch(void* const* d_in, const int* in_sizes, int n_in,
                              void* d_out, int out_size)
{
    const float* cur_fea = (const float*)d_in[0];
    const float* n1w = (const float*)d_in[1];
    const float* n1b = (const float*)d_in[2];
    const float* n2w = (const float*)d_in[3];
    const float* n2b = (const float*)d_in[4];
    const float* c_w1 = (const float*)d_in[5];  const float* c_b1 = (const float*)d_in[6];
    const float* c_w2 = (const float*)d_in[7];  const float* c_b2 = (const float*)d_in[8];
    const float* m_w1 = (const float*)d_in[9];  const float* m_b1 = (const float*)d_in[10];
    const float* m_w2 = (const float*)d_in[11]; const float* m_b2 = (const float*)d_in[12];
    const float* p_w1 = (const float*)d_in[13]; const float* p_b1 = (const float*)d_in[14];
    const float* p_w2 = (const float*)d_in[15]; const float* p_b2 = (const float*)d_in[16];
    const float* q_w = (const float*)d_in[17];  const float* q_b = (const float*)d_in[18];
    const float* k_w = (const float*)d_in[19];  const float* k_b = (const float*)d_in[20];

    cudaFuncSetAttribute((const void*)gemm_mma<128, 256, 4, 8>,
                         cudaFuncAttributeMaxDynamicSharedMemorySize, SMEM_BIG);
    cudaFuncSetAttribute((const void*)gemm_mma<64, 128, 2, 4>,
                         cudaFuncAttributeMaxDynamicSharedMemorySize, SMEM_SM);
    cudaFuncSetAttribute((const void*)gemm_bat,
                         cudaFuncAttributeMaxDynamicSharedMemorySize, SMEM_BAT);

    float *x, *cg, *memh, *qb, *kb, *o, *c2, *gate, *ap, *bias2, *memA, *memB;
    cudaGetSymbolAddress((void**)&x, g_x);       cudaGetSymbolAddress((void**)&cg, g_cg);
    cudaGetSymbolAddress((void**)&memh, g_memh); cudaGetSymbolAddress((void**)&qb, g_q);
    cudaGetSymbolAddress((void**)&kb, g_kk);     cudaGetSymbolAddress((void**)&o, g_o);
    cudaGetSymbolAddress((void**)&c2, g_c2);     cudaGetSymbolAddress((void**)&gate, g_gate);
    cudaGetSymbolAddress((void**)&ap, g_ap);     cudaGetSymbolAddress((void**)&bias2, g_bias2);
    cudaGetSymbolAddress((void**)&memA, g_memA); cudaGetSymbolAddress((void**)&memB, g_memB);

    uint16_t *xA, *hidA, *cgA, *cA, *memAg, *Q3, *K3, *oT3, *cgT3;
    uint16_t *wc1, *wc2, *wm1, *wm2, *wp1, *wp2, *wq, *wk;
    cudaGetSymbolAddress((void**)&xA, g_xA);     cudaGetSymbolAddress((void**)&hidA, g_hidA);
    cudaGetSymbolAddress((void**)&cgA, g_cgA);   cudaGetSymbolAddress((void**)&cA, g_cA);
    cudaGetSymbolAddress((void**)&memAg, g_memAg);
    cudaGetSymbolAddress((void**)&Q3, g_Q3);     cudaGetSymbolAddress((void**)&K3, g_K3);
    cudaGetSymbolAddress((void**)&oT3, g_oT3);   cudaGetSymbolAddress((void**)&cgT3, g_cgT3);
    cudaGetSymbolAddress((void**)&wc1, g_wc1);   cudaGetSymbolAddress((void**)&wc2, g_wc2);
    cudaGetSymbolAddress((void**)&wm1, g_wm1);   cudaGetSymbolAddress((void**)&wm2, g_wm2);
    cudaGetSymbolAddress((void**)&wp1, g_wp1);   cudaGetSymbolAddress((void**)&wp2, g_wp2);
    cudaGetSymbolAddress((void**)&wq, g_wq);     cudaGetSymbolAddress((void**)&wk, g_wk);

    dim3 wb(32, 8);
    wsplitT<<<dim3(HID_/32, C_/32),   wb>>>(c_w1, wc1, C_, HID_);   // top 768 rows only
    wsplitT<<<dim3(C_/32, HID_/32),   wb>>>(c_w2, wc2, HID_, C_);
    wsplitT<<<dim3(HID_/32, C_/32),   wb>>>(m_w1, wm1, C_, HID_);
    wsplitT<<<dim3(C_/32, HID_/32),   wb>>>(m_w2, wm2, HID_, C_);
    wsplitT<<<dim3(HID_/32, C_/32),   wb>>>(p_w1, wp1, C_, HID_);
    wsplitT<<<dim3(C_/32, HID_/32),   wb>>>(p_w2, wp2, HID_, C_);
    wsplitT<<<dim3(C_/32, C_/32),     wb>>>(q_w, wq, C_, C_);
    wsplitT<<<dim3(C_/32, C_/32),     wb>>>(k_w, wk, C_, C_);

    ln_kernel<<<B_*T_*N_, 256>>>(cur_fea, n1w, n1b, x, xA);
    initmem_kernel<<<(B_*MEM_*C_/2 + 255)/256, 256>>>(x, memA, memAg);

    float* mcur = memA;
    float* mnxt = memB;

    for (int t = 1; t < T_; t++) {
        ap_kernel<<<(B_*C_ + 255)/256, 256>>>(mcur, ap);
        apw_kernel<<<dim3(HID_/256, B_), 256>>>(ap, c_w1, c_b1, bias2);

        const uint16_t* feaA = xA + (size_t)t * ROWS_ * 3 * C_;
        gemm_big(feaA, wc1, bias2, nullptr, hidA, ROWS_, HID_, C_, 1|4|8); // fc1_c (K=768!)
        gemm_sm (hidA, wc2, c_b2, cg, cgA, ROWS_, C_, HID_, 2|4);          // fc2_c
        gemm_big(memAg, wm1, m_b1, nullptr, hidA, ROWS_, HID_, C_, 1|4);   // fc1_m
        gemm_sm (hidA, wm2, m_b2, memh, nullptr, ROWS_, C_, HID_, 2);      // fc2_m
        gemm_sm (memAg, wk, k_b, kb, nullptr, ROWS_, C_, C_, 2);           // k
        gemm_sm (cgA, wq, q_b, qb, nullptr, ROWS_, C_, C_, 2);             // q

        pack_qk<<<(64*196*192 + 255)/256, 256>>>(qb, Q3, 0);
        pack_qk<<<(64*196*192 + 255)/256, 256>>>(kb, K3, 1);
        gemm_bat<<<dim3(2, 2, 64), 256, SMEM_BAT>>>(
            (const bf16*)Q3, (const bf16*)K3, o, nullptr, 196, 196, 384, 0);
        gate_kernel<<<(B_*H_*MEM_ + 255)/256, 256>>>(o, gate);
        pack_oT<<<dim3(7, 8, 64), wb>>>(o, oT3);
        pack_cgT<<<dim3(3, 8, 64), wb>>>(cg, cgT3);
        gemm_bat<<<dim3(1, 2, 64), 256, SMEM_BAT>>>(
            (const bf16*)oT3, (const bf16*)cgT3, nullptr, cA, 196, 96, 768, 1);

        gemm_big(cA, wp1, p_b1, nullptr, hidA, ROWS_, HID_, C_, 1|4);      // fc1_p
        gemm_sm (hidA, wp2, p_b2, c2, nullptr, ROWS_, C_, HID_, 2);        // fc2_p

        float* dst = (t == T_ - 1) ? (float*)d_out : mnxt;
        final_kernel<<<B_*MEM_, 256>>>(c2, gate, memh, n2w, n2b, dst, memAg);

        float* tmp = mcur; mcur = mnxt; mnxt = tmp;
    }
}

// round 8
// speedup vs baseline: 2.4771x; 1.0644x over previous
#include <cuda_runtime.h>
#include <cuda_bf16.h>
#include <math.h>
#include <stdint.h>

#define B_   8
#define T_   16
#define N_   196
#define C_   768
#define H_   8
#define D_   96
#define MEM_ 196
#define HID_ 3072
#define ROWS_ 1568
#define SCALE_ 0.1020620726159657f

typedef __nv_bfloat16 bf16;

// ---------------- fp32 scratch ----------------
__device__ __align__(256) float g_x   [B_*T_*N_*C_];
__device__ __align__(256) float g_cg  [ROWS_*C_];
__device__ __align__(256) float g_memh[ROWS_*C_];
__device__ __align__(256) float g_q   [ROWS_*C_];
__device__ __align__(256) float g_kk  [ROWS_*C_];
__device__ __align__(256) float g_o   [B_*H_*N_*MEM_];
__device__ __align__(256) float g_c2  [ROWS_*C_];
__device__ __align__(256) float g_gate[B_*H_*MEM_];
__device__ __align__(256) float g_bias2[B_*HID_];
__device__ __align__(256) float g_memA[ROWS_*C_];
__device__ __align__(256) float g_memB[ROWS_*C_];

// ---------------- augmented bf16 activations ----------------
__device__ __align__(256) uint16_t g_xA  [T_*B_*N_*3*C_];   // [t][b][n][hi|hi|lo]
__device__ __align__(256) uint16_t g_hidCA[ROWS_*3*HID_];   // c/p-chain hidden
__device__ __align__(256) uint16_t g_hidMA[ROWS_*3*HID_];   // m-chain hidden
__device__ __align__(256) uint16_t g_cgA [ROWS_*3*C_];
__device__ __align__(256) uint16_t g_cA  [ROWS_*3*C_];
__device__ __align__(256) uint16_t g_memAg[ROWS_*3*C_];

// attention aug operands
__device__ __align__(256) uint16_t g_Q3 [64*196*384];
__device__ __align__(256) uint16_t g_K3 [64*196*384];
__device__ __align__(256) uint16_t g_oT3[64*196*768];
__device__ __align__(256) uint16_t g_cgT3[64*96*768];

// weights augmented [N][3K] = [hi|lo|hi]
__device__ __align__(256) uint16_t g_wc1[HID_*3*C_];
__device__ __align__(256) uint16_t g_wc2[C_*3*HID_];
__device__ __align__(256) uint16_t g_wm1[HID_*3*C_];
__device__ __align__(256) uint16_t g_wm2[C_*3*HID_];
__device__ __align__(256) uint16_t g_wp1[HID_*3*C_];
__device__ __align__(256) uint16_t g_wp2[C_*3*HID_];
__device__ __align__(256) uint16_t g_wq [C_*3*C_];
__device__ __align__(256) uint16_t g_wk [C_*3*C_];

__device__ __forceinline__ float gelu_exact(float x) {
    return 0.5f * x * (1.0f + erff(x * 0.70710678118654752f));
}
__device__ __forceinline__ uint32_t smem_u32(const void* p) {
    uint32_t a;
    asm("{ .reg .u64 t; cvta.to.shared.u64 t, %1; cvt.u32.u64 %0, t; }" : "=r"(a) : "l"(p));
    return a;
}
__device__ __forceinline__ void cp16(uint32_t dst, const void* src, int pred) {
    int sz = pred ? 16 : 0;
    asm volatile("cp.async.cg.shared.global [%0], [%1], 16, %2;" :: "r"(dst), "l"(src), "r"(sz) : "memory");
}
__device__ __forceinline__ uint32_t swz(uint32_t o) { return o ^ ((o >> 3) & 0x70); }

#define LDSM4(r0, r1, r2, r3, addr) \
    asm volatile("ldmatrix.sync.aligned.m8n8.x4.shared.b16 {%0,%1,%2,%3}, [%4];" \
        : "=r"(r0), "=r"(r1), "=r"(r2), "=r"(r3) : "r"(addr))

#define MMA16816(d, a, b0, b1) \
    asm volatile("mma.sync.aligned.m16n8k16.row.col.f32.bf16.bf16.f32 " \
        "{%0,%1,%2,%3}, {%4,%5,%6,%7}, {%8,%9}, {%0,%1,%2,%3};" \
        : "+f"((d)[0]), "+f"((d)[1]), "+f"((d)[2]), "+f"((d)[3]) \
        : "r"((a)[0]), "r"((a)[1]), "r"((a)[2]), "r"((a)[3]), "r"(b0), "r"(b1))

__device__ __forceinline__ void aug_store(uint16_t* aug, size_t base, int Ncols, int col,
                                          float v0, float v1)
{
    bf16 h0 = __float2bfloat16(v0), h1 = __float2bfloat16(v1);
    __nv_bfloat162 hh = __halves2bfloat162(h0, h1);
    __nv_bfloat162 ll = __halves2bfloat162(__float2bfloat16(v0 - __bfloat162float(h0)),
                                           __float2bfloat16(v1 - __bfloat162float(h1)));
    *(uint32_t*)(aug + base + col)             = *(uint32_t*)&hh;
    *(uint32_t*)(aug + base + Ncols + col)     = *(uint32_t*)&hh;
    *(uint32_t*)(aug + base + 2 * Ncols + col) = *(uint32_t*)&ll;
}

// ==================== weight-vs-activation GEMM ====================
// mode bits: 1=gelu, 2=write fp32 out, 4=write aug, 8=per-batch bias (row/196)
#define GS 3

template<int BM, int BN, int MT, int NT>
__global__ __launch_bounds__(256) void gemm_mma(
    const bf16* __restrict__ A, const bf16* __restrict__ Bw,
    const float* __restrict__ bias, float* __restrict__ out,
    uint16_t* __restrict__ outAug, int M, int N, int K3, int mode)
{
    constexpr int A_BYTES = BM * 128;
    constexpr int STG = (BM + BN) * 128;
    extern __shared__ __align__(1024) char smem[];
    uint32_t sb = smem_u32(smem);
    int tid = threadIdx.x, wid = tid >> 5, lane = tid & 31;
    int bm = blockIdx.y * BM, bn = blockIdx.x * BN;
    int m0w = (wid & 1) * (MT * 16);
    int n0w = (wid >> 1) * (NT * 8);
    int NC = K3 >> 6;

    auto load_stage = [&](int c) {
        uint32_t stage = sb + (c % GS) * STG;
        int k0 = c << 6;
        constexpr int TOT = (BM + BN) * 8;
#pragma unroll
        for (int g0 = 0; g0 < TOT; g0 += 256) {
            int g = g0 + tid;
            int isB = (g >= BM * 8);
            int q = isB ? (g - BM * 8) : g;
            int row = q >> 3, c16 = q & 7;
            uint32_t dst = stage + (isB ? A_BYTES : 0) + swz((row << 7) + (c16 << 4));
            const bf16* src;
            int pred = 1;
            if (!isB) {
                int gr = bm + row; pred = gr < M;
                src = A + (size_t)(pred ? gr : 0) * K3 + k0 + (c16 << 3);
            } else {
                int gr = bn + row;
                src = Bw + (size_t)gr * K3 + k0 + (c16 << 3);
            }
            cp16(dst, src, pred);
        }
        asm volatile("cp.async.commit_group;" ::: "memory");
    };

    float acc[MT][NT][4];
#pragma unroll
    for (int mt = 0; mt < MT; mt++)
#pragma unroll
        for (int nt = 0; nt < NT; nt++)
#pragma unroll
            for (int i = 0; i < 4; i++) acc[mt][nt][i] = 0.f;

    load_stage(0);
    load_stage(1);

    for (int c = 0; c < NC; c++) {
        if (c == NC - 1) asm volatile("cp.async.wait_group 0;" ::: "memory");
        else             asm volatile("cp.async.wait_group 1;" ::: "memory");
        __syncthreads();
        if (c + 2 < NC) load_stage(c + 2);

        uint32_t sA = sb + (c % GS) * STG;
        uint32_t sB = sA + A_BYTES;
#pragma unroll
        for (int ks = 0; ks < 4; ks++) {
            uint32_t a[MT][4], bfr[NT / 2][4];
#pragma unroll
            for (int mt = 0; mt < MT; mt++) {
                int row = m0w + mt * 16 + (lane & 15);
                int ch = ks * 2 + (lane >> 4);
                uint32_t ad = sA + swz((uint32_t)(row << 7) + (ch << 4));
                LDSM4(a[mt][0], a[mt][1], a[mt][2], a[mt][3], ad);
            }
#pragma unroll
            for (int bp = 0; bp < NT / 2; bp++) {
                int row = n0w + bp * 16 + (lane & 7) + ((lane & 16) >> 1);
                int ch = ks * 2 + ((lane & 8) >> 3);
                uint32_t ad = sB + swz((uint32_t)(row << 7) + (ch << 4));
                LDSM4(bfr[bp][0], bfr[bp][1], bfr[bp][2], bfr[bp][3], ad);
            }
#pragma unroll
            for (int mt = 0; mt < MT; mt++)
#pragma unroll
                for (int nt = 0; nt < NT; nt++)
                    MMA16816(acc[mt][nt], a[mt],
                             bfr[nt >> 1][(nt & 1) * 2], bfr[nt >> 1][(nt & 1) * 2 + 1]);
        }
    }

#pragma unroll
    for (int mt = 0; mt < MT; mt++) {
        int r0 = bm + m0w + mt * 16 + (lane >> 2);
        int r1 = r0 + 8;
#pragma unroll
        for (int nt = 0; nt < NT; nt++) {
            int col = bn + n0w + nt * 8 + ((lane & 3) << 1);
            if (r0 < M) {
                int bb = (mode & 8) ? (r0 / 196) * N : 0;
                float v0 = acc[mt][nt][0] + bias[bb + col];
                float v1 = acc[mt][nt][1] + bias[bb + col + 1];
                if (mode & 1) { v0 = gelu_exact(v0); v1 = gelu_exact(v1); }
                if (mode & 2) *(float2*)(out + (size_t)r0 * N + col) = make_float2(v0, v1);
                if (mode & 4) aug_store(outAug, (size_t)r0 * 3 * N, N, col, v0, v1);
            }
            if (r1 < M) {
                int bb = (mode & 8) ? (r1 / 196) * N : 0;
                float v2 = acc[mt][nt][2] + bias[bb + col];
                float v3 = acc[mt][nt][3] + bias[bb + col + 1];
                if (mode & 1) { v2 = gelu_exact(v2); v3 = gelu_exact(v3); }
                if (mode & 2) *(float2*)(out + (size_t)r1 * N + col) = make_float2(v2, v3);
                if (mode & 4) aug_store(outAug, (size_t)r1 * 3 * N, N, col, v2, v3);
            }
        }
    }
}

// ==================== batched aug GEMM for attention ====================
__global__ __launch_bounds__(256) void gemm_bat(
    const bf16* __restrict__ Aall, const bf16* __restrict__ Ball,
    float* __restrict__ oOut, uint16_t* __restrict__ cAug,
    int MA, int NB, int K3, int epi)
{
    constexpr int BM = 128, BN = 128, MT = 4, NT = 4;
    constexpr int A_BYTES = BM * 128;
    constexpr int STG = (BM + BN) * 128;
    extern __shared__ __align__(1024) char smem[];
    uint32_t sb = smem_u32(smem);
    int tid = threadIdx.x, wid = tid >> 5, lane = tid & 31;
    int bz = blockIdx.z;
    const bf16* A = Aall + (size_t)bz * MA * K3;
    const bf16* Bw = Ball + (size_t)bz * NB * K3;
    int bm = blockIdx.y * BM, bn = blockIdx.x * BN;
    int m0w = (wid & 1) * 64;
    int n0w = (wid >> 1) * 32;
    int NC = K3 >> 6;

    auto load_stage = [&](int c) {
        uint32_t stage = sb + (c % GS) * STG;
        int k0 = c << 6;
#pragma unroll
        for (int g0 = 0; g0 < (BM + BN) * 8; g0 += 256) {
            int g = g0 + tid;
            int isB = (g >= BM * 8);
            int q = isB ? (g - BM * 8) : g;
            int row = q >> 3, c16 = q & 7;
            uint32_t dst = stage + (isB ? A_BYTES : 0) + swz((row << 7) + (c16 << 4));
            const bf16* src;
            int pred;
            if (!isB) {
                int gr = bm + row; pred = gr < MA;
                src = A + (size_t)(pred ? gr : 0) * K3 + k0 + (c16 << 3);
            } else {
                int gr = bn + row; pred = gr < NB;
                src = Bw + (size_t)(pred ? gr : 0) * K3 + k0 + (c16 << 3);
            }
            cp16(dst, src, pred);
        }
        asm volatile("cp.async.commit_group;" ::: "memory");
    };

    float acc[MT][NT][4];
#pragma unroll
    for (int mt = 0; mt < MT; mt++)
#pragma unroll
        for (int nt = 0; nt < NT; nt++)
#pragma unroll
            for (int i = 0; i < 4; i++) acc[mt][nt][i] = 0.f;

    load_stage(0);
    load_stage(1);

    for (int c = 0; c < NC; c++) {
        if (c == NC - 1) asm volatile("cp.async.wait_group 0;" ::: "memory");
        else             asm volatile("cp.async.wait_group 1;" ::: "memory");
        __syncthreads();
        if (c + 2 < NC) load_stage(c + 2);

        uint32_t sA = sb + (c % GS) * STG;
        uint32_t sB = sA + A_BYTES;
#pragma unroll
        for (int ks = 0; ks < 4; ks++) {
            uint32_t a[MT][4], bfr[NT / 2][4];
#pragma unroll
            for (int mt = 0; mt < MT; mt++) {
                int row = m0w + mt * 16 + (lane & 15);
                int ch = ks * 2 + (lane >> 4);
                uint32_t ad = sA + swz((uint32_t)(row << 7) + (ch << 4));
                LDSM4(a[mt][0], a[mt][1], a[mt][2], a[mt][3], ad);
            }
#pragma unroll
            for (int bp = 0; bp < NT / 2; bp++) {
                int row = n0w + bp * 16 + (lane & 7) + ((lane & 16) >> 1);
                int ch = ks * 2 + ((lane & 8) >> 3);
                uint32_t ad = sB + swz((uint32_t)(row << 7) + (ch << 4));
                LDSM4(bfr[bp][0], bfr[bp][1], bfr[bp][2], bfr[bp][3], ad);
            }
#pragma unroll
            for (int mt = 0; mt < MT; mt++)
#pragma unroll
                for (int nt = 0; nt < NT; nt++)
                    MMA16816(acc[mt][nt], a[mt],
                             bfr[nt >> 1][(nt & 1) * 2], bfr[nt >> 1][(nt & 1) * 2 + 1]);
        }
    }

    int bb = bz >> 3, hh = bz & 7;
#pragma unroll
    for (int mt = 0; mt < MT; mt++) {
        int r0 = bm + m0w + mt * 16 + (lane >> 2);
        int r1 = r0 + 8;
#pragma unroll
        for (int nt = 0; nt < NT; nt++) {
            int col = bn + n0w + nt * 8 + ((lane & 3) << 1);
            float v0 = acc[mt][nt][0], v1 = acc[mt][nt][1];
            float v2 = acc[mt][nt][2], v3 = acc[mt][nt][3];
            if (epi == 0) {
                if (col + 1 < 196) {
                    if (r0 < 196) {
                        float2 w = make_float2(1.f/(1.f+expf(-v0*SCALE_)),
                                               1.f/(1.f+expf(-v1*SCALE_)));
                        *(float2*)(oOut + ((size_t)bz*196 + r0)*196 + col) = w;
                    }
                    if (r1 < 196) {
                        float2 w = make_float2(1.f/(1.f+expf(-v2*SCALE_)),
                                               1.f/(1.f+expf(-v3*SCALE_)));
                        *(float2*)(oOut + ((size_t)bz*196 + r1)*196 + col) = w;
                    }
                }
            } else {
                if (col + 1 < 96) {
                    if (r0 < 196)
                        aug_store(cAug, (size_t)(bb*196 + r0) * 3 * C_, C_, hh*96 + col, v0, v1);
                    if (r1 < 196)
                        aug_store(cAug, (size_t)(bb*196 + r1) * 3 * C_, C_, hh*96 + col, v2, v3);
                }
            }
        }
    }
}

// W [K][N] fp32 -> aug bf16 [N][3K] = [hi|lo|hi] (first K rows of w only)
__global__ void wsplitT(const float* __restrict__ w, uint16_t* __restrict__ aug,
                        int K, int N)
{
    __shared__ float t[32][33];
    int n0 = blockIdx.x * 32, k0 = blockIdx.y * 32;
    int tx = threadIdx.x, ty = threadIdx.y;
#pragma unroll
    for (int j = 0; j < 4; j++)
        t[ty + 8 * j][tx] = w[(size_t)(k0 + ty + 8 * j) * N + n0 + tx];
    __syncthreads();
#pragma unroll
    for (int j = 0; j < 4; j++) {
        float v = t[tx][ty + 8 * j];
        int n = n0 + ty + 8 * j, k = k0 + tx;
        bf16 h = __float2bfloat16(v);
        bf16 l = __float2bfloat16(v - __bfloat162float(h));
        size_t base = (size_t)n * 3 * K;
        *(bf16*)(aug + base + k)         = h;
        *(bf16*)(aug + base + K + k)     = l;
        *(bf16*)(aug + base + 2 * K + k) = h;
    }
}

// ==================== pack kernels for attention ====================
__global__ void pack_qk(const float* __restrict__ src, uint16_t* __restrict__ dst, int isK)
{
    int idx = blockIdx.x * 256 + threadIdx.x;
    if (idx >= 64 * 196 * 192) return;
    int c = idx % 192, row = idx / 192;
    int bh = row / 196, n = row % 196;
    int b = bh >> 3, h = bh & 7;
    int s = c >> 6, d = (c & 63) * 2;
    uint32_t val = 0;
    if (d < 96) {
        float2 v = *(const float2*)(src + ((size_t)b*196 + n)*768 + h*96 + d);
        bf16 h0 = __float2bfloat16(v.x), h1 = __float2bfloat16(v.y);
        int isLo = isK ? (s == 1) : (s == 2);
        __nv_bfloat162 pk;
        if (isLo)
            pk = __halves2bfloat162(__float2bfloat16(v.x - __bfloat162float(h0)),
                                    __float2bfloat16(v.y - __bfloat162float(h1)));
        else
            pk = __halves2bfloat162(h0, h1);
        val = *(uint32_t*)&pk;
    }
    ((uint32_t*)dst)[(size_t)row * 192 + c] = val;
}

__global__ void pack_oT(const float* __restrict__ o, uint16_t* __restrict__ dst)
{
    __shared__ float t[32][33];
    int bh = blockIdx.z, m0 = blockIdx.x * 32, n0 = blockIdx.y * 32;
    int tx = threadIdx.x, ty = threadIdx.y;
#pragma unroll
    for (int j = 0; j < 4; j++) {
        int n = n0 + ty + 8 * j, m = m0 + tx;
        t[ty + 8 * j][tx] = (n < 196 && m < 196) ? o[((size_t)bh*196 + n)*196 + m] : 0.f;
    }
    __syncthreads();
#pragma unroll
    for (int j = 0; j < 4; j++) {
        int m = m0 + ty + 8 * j, n = n0 + tx;
        if (m < 196) {
            float v = t[tx][ty + 8 * j];
            bf16 h = __float2bfloat16(v);
            bf16 l = __float2bfloat16(v - __bfloat162float(h));
            size_t base = ((size_t)bh*196 + m) * 768;
            dst[base + n]       = *(uint16_t*)&h;
            dst[base + 256 + n] = *(uint16_t*)&h;
            dst[base + 512 + n] = *(uint16_t*)&l;
        }
    }
}

__global__ void pack_cgT(const float* __restrict__ cg, uint16_t* __restrict__ dst)
{
    __shared__ float t[32][33];
    int bh = blockIdx.z, d0 = blockIdx.x * 32, n0 = blockIdx.y * 32;
    int b = bh >> 3, h = bh & 7;
    int tx = threadIdx.x, ty = threadIdx.y;
#pragma unroll
    for (int j = 0; j < 4; j++) {
        int n = n0 + ty + 8 * j;
        t[ty + 8 * j][tx] = (n < 196) ? cg[((size_t)b*196 + n)*768 + h*96 + d0 + tx] : 0.f;
    }
    __syncthreads();
#pragma unroll
    for (int j = 0; j < 4; j++) {
        int d = d0 + ty + 8 * j, n = n0 + tx;
        float v = t[tx][ty + 8 * j];
        bf16 hv = __float2bfloat16(v);
        bf16 lv = __float2bfloat16(v - __bfloat162float(hv));
        size_t base = ((size_t)bh*96 + d) * 768;
        dst[base + n]       = *(uint16_t*)&hv;
        dst[base + 256 + n] = *(uint16_t*)&lv;
        dst[base + 512 + n] = *(uint16_t*)&hv;
    }
}

// ==================== elementwise kernels ====================
__global__ __launch_bounds__(256) void ln_kernel(
    const float* __restrict__ x, const float* __restrict__ w,
    const float* __restrict__ b, float* __restrict__ y, uint16_t* __restrict__ xA)
{
    int row = blockIdx.x;
    int bb = row / (T_ * N_);
    int t  = (row / N_) % T_;
    int n  = row % N_;
    size_t xrow = ((size_t)(t * B_ + bb) * N_ + n) * 3 * C_;
    const float* xr = x + (size_t)row * C_;
    float v[3], s = 0.f, s2 = 0.f;
#pragma unroll
    for (int i = 0; i < 3; i++) { v[i] = xr[threadIdx.x + i*256]; s += v[i]; s2 += v[i]*v[i]; }
    __shared__ float red[18];
#pragma unroll
    for (int off = 16; off; off >>= 1) {
        s  += __shfl_down_sync(0xffffffffu, s, off);
        s2 += __shfl_down_sync(0xffffffffu, s2, off);
    }
    int wid = threadIdx.x >> 5, lane = threadIdx.x & 31;
    if (lane == 0) { red[wid] = s; red[8+wid] = s2; }
    __syncthreads();
    if (threadIdx.x == 0) {
        float ts = 0.f, ts2 = 0.f;
        for (int i = 0; i < 8; i++) { ts += red[i]; ts2 += red[8+i]; }
        red[16] = ts; red[17] = ts2;
    }
    __syncthreads();
    float mean = red[16] * (1.0f/C_);
    float inv  = rsqrtf(red[17] * (1.0f/C_) - mean*mean + 1e-5f);
    float* yr = y + (size_t)row * C_;
#pragma unroll
    for (int i = 0; i < 3; i++) {
        int c = threadIdx.x + i*256;
        float o = (v[i] - mean) * inv * w[c] + b[c];
        yr[c] = o;
        bf16 h = __float2bfloat16(o);
        xA[xrow + c]         = *(uint16_t*)&h;
        xA[xrow + C_ + c]    = *(uint16_t*)&h;
        bf16 l = __float2bfloat16(o - __bfloat162float(h));
        xA[xrow + 2*C_ + c]  = *(uint16_t*)&l;
    }
}

// fused: ap[b] = mean_M(mem[b]) computed in smem, then
// bias2[b][j] = c_b1[j] + sum_k ap[b][k] * c_w1[768+k][j]
__global__ __launch_bounds__(256) void apw_fused(
    const float* __restrict__ mem, const float* __restrict__ c_w1,
    const float* __restrict__ c_b1, float* __restrict__ bias2)
{
    int b = blockIdx.y;
    int j = blockIdx.x * 256 + threadIdx.x;
    __shared__ float aps[768];
    for (int k = threadIdx.x; k < 768; k += 256) {
        float s = 0.f;
        const float* p = mem + (size_t)b * MEM_ * C_ + k;
#pragma unroll 4
        for (int m = 0; m < MEM_; m++) s += p[(size_t)m * C_];
        aps[k] = s * (1.0f / MEM_);
    }
    __syncthreads();
    float acc = c_b1[j];
    const float* wp = c_w1 + (size_t)768 * HID_ + j;
#pragma unroll 8
    for (int k = 0; k < 768; k++)
        acc = fmaf(aps[k], wp[(size_t)k * HID_], acc);
    bias2[b * HID_ + j] = acc;
}

__global__ __launch_bounds__(256) void final_kernel(
    const float* __restrict__ c2, const float* __restrict__ gate,
    const float* __restrict__ memh, const float* __restrict__ w,
    const float* __restrict__ bb, float* __restrict__ y, uint16_t* __restrict__ aug)
{
    int row = blockIdx.x;
    int b = row / MEM_, m = row % MEM_;
    float v[3], s = 0.f, s2 = 0.f;
#pragma unroll
    for (int i = 0; i < 3; i++) {
        int c = threadIdx.x + i*256;
        float g = gate[(b*H_ + (c/D_))*MEM_ + m];
        v[i] = c2[(size_t)row*C_ + c] + g * memh[(size_t)row*C_ + c];
        s += v[i]; s2 += v[i]*v[i];
    }
    __shared__ float red[18];
#pragma unroll
    for (int off = 16; off; off >>= 1) {
        s  += __shfl_down_sync(0xffffffffu, s, off);
        s2 += __shfl_down_sync(0xffffffffu, s2, off);
    }
    int wid = threadIdx.x >> 5, lane = threadIdx.x & 31;
    if (lane == 0) { red[wid] = s; red[8+wid] = s2; }
    __syncthreads();
    if (threadIdx.x == 0) {
        float ts = 0.f, ts2 = 0.f;
        for (int i = 0; i < 8; i++) { ts += red[i]; ts2 += red[8+i]; }
        red[16] = ts; red[17] = ts2;
    }
    __syncthreads();
    float mean = red[16] * (1.0f/C_);
    float inv  = rsqrtf(red[17] * (1.0f/C_) - mean*mean + 1e-5f);
    float* yr = y + (size_t)row * C_;
    size_t base = (size_t)row * 3 * C_;
#pragma unroll
    for (int i = 0; i < 3; i++) {
        int c = threadIdx.x + i*256;
        float o = (v[i] - mean) * inv * w[c] + bb[c];
        yr[c] = o;
        bf16 h = __float2bfloat16(o);
        aug[base + c]        = *(uint16_t*)&h;
        aug[base + C_ + c]   = *(uint16_t*)&h;
        bf16 l = __float2bfloat16(o - __bfloat162float(h));
        aug[base + 2*C_ + c] = *(uint16_t*)&l;
    }
}

__global__ void initmem_kernel(const float* __restrict__ x, float* __restrict__ mem,
                               uint16_t* __restrict__ aug)
{
    int idx = blockIdx.x * 256 + threadIdx.x;
    if (idx >= B_*MEM_*C_/2) return;
    int row = idx / (C_/2), jp = (idx % (C_/2)) * 2;
    int b = row / MEM_, r = row % MEM_;
    float2 v = *(const float2*)(x + (size_t)b*T_*N_*C_ + (size_t)r*C_ + jp);
    *(float2*)(mem + (size_t)row*C_ + jp) = v;
    aug_store(aug, (size_t)row * 3 * C_, C_, jp, v.x, v.y);
}

__global__ void gate_kernel(const float* __restrict__ o, float* __restrict__ gate)
{
    int idx = blockIdx.x * 256 + threadIdx.x;
    if (idx >= B_*H_*MEM_) return;
    int m = idx % MEM_, bh = idx / MEM_;
    const float* op = o + (size_t)bh*N_*MEM_ + m;
    float s = 0.f;
    for (int n = 0; n < N_; n++) s += op[(size_t)n*MEM_];
    gate[idx] = 1.0f - s * (1.0f/N_);
}

// ==================== host orchestration ====================
#define SMEM_BIG (GS * (128 + 256) * 128)   // 147456
#define SMEM_SM  (GS * (64 + 128) * 128)    // 73728
#define SMEM_BAT (GS * (128 + 128) * 128)   // 98304

static void gemm_big(const uint16_t* a, const uint16_t* w, const float* bias,
                     float* out, uint16_t* outAug, int M, int N, int K, int mode,
                     cudaStream_t st)
{
    dim3 g(N / 256, (M + 127) / 128);
    gemm_mma<128, 256, 4, 8><<<g, 256, SMEM_BIG, st>>>(
        (const bf16*)a, (const bf16*)w, bias, out, outAug, M, N, 3 * K, mode);
}
static void gemm_sm(const uint16_t* a, const uint16_t* w, const float* bias,
                    float* out, uint16_t* outAug, int M, int N, int K, int mode,
                    cudaStream_t st)
{
    dim3 g(N / 128, (M + 63) / 64);
    gemm_mma<64, 128, 2, 4><<<g, 256, SMEM_SM, st>>>(
        (const bf16*)a, (const bf16*)w, bias, out, outAug, M, N, 3 * K, mode);
}

extern "C" void kernel_launch(void* const* d_in, const int* in_sizes, int n_in,
                              void* d_out, int out_size)
{
    const float* cur_fea = (const float*)d_in[0];
    const float* n1w = (const float*)d_in[1];
    const float* n1b = (const float*)d_in[2];
    const float* n2w = (const float*)d_in[3];
    const float* n2b = (const float*)d_in[4];
    const float* c_w1 = (const float*)d_in[5];  const float* c_b1 = (const float*)d_in[6];
    const float* c_w2 = (const float*)d_in[7];  const float* c_b2 = (const float*)d_in[8];
    const float* m_w1 = (const float*)d_in[9];  const float* m_b1 = (const float*)d_in[10];
    const float* m_w2 = (const float*)d_in[11]; const float* m_b2 = (const float*)d_in[12];
    const float* p_w1 = (const float*)d_in[13]; const float* p_b1 = (const float*)d_in[14];
    const float* p_w2 = (const float*)d_in[15]; const float* p_b2 = (const float*)d_in[16];
    const float* q_w = (const float*)d_in[17];  const float* q_b = (const float*)d_in[18];
    const float* k_w = (const float*)d_in[19];  const float* k_b = (const float*)d_in[20];

    cudaFuncSetAttribute((const void*)gemm_mma<128, 256, 4, 8>,
                         cudaFuncAttributeMaxDynamicSharedMemorySize, SMEM_BIG);
    cudaFuncSetAttribute((const void*)gemm_mma<64, 128, 2, 4>,
                         cudaFuncAttributeMaxDynamicSharedMemorySize, SMEM_SM);
    cudaFuncSetAttribute((const void*)gemm_bat,
                         cudaFuncAttributeMaxDynamicSharedMemorySize, SMEM_BAT);

    // second stream + events (created once; resources only, identical work per call)
    static cudaStream_t sS = nullptr;
    static cudaEvent_t eA, eK, eCG, eS2;
    if (!sS) {
        cudaStreamCreateWithFlags(&sS, cudaStreamNonBlocking);
        cudaEventCreateWithFlags(&eA,  cudaEventDisableTiming);
        cudaEventCreateWithFlags(&eK,  cudaEventDisableTiming);
        cudaEventCreateWithFlags(&eCG, cudaEventDisableTiming);
        cudaEventCreateWithFlags(&eS2, cudaEventDisableTiming);
    }

    float *x, *cg, *memh, *qb, *kb, *o, *c2, *gate, *bias2, *memA, *memB;
    cudaGetSymbolAddress((void**)&x, g_x);       cudaGetSymbolAddress((void**)&cg, g_cg);
    cudaGetSymbolAddress((void**)&memh, g_memh); cudaGetSymbolAddress((void**)&qb, g_q);
    cudaGetSymbolAddress((void**)&kb, g_kk);     cudaGetSymbolAddress((void**)&o, g_o);
    cudaGetSymbolAddress((void**)&c2, g_c2);     cudaGetSymbolAddress((void**)&gate, g_gate);
    cudaGetSymbolAddress((void**)&bias2, g_bias2);
    cudaGetSymbolAddress((void**)&memA, g_memA); cudaGetSymbolAddress((void**)&memB, g_memB);

    uint16_t *xA, *hidCA, *hidMA, *cgA, *cA, *memAg, *Q3, *K3, *oT3, *cgT3;
    uint16_t *wc1, *wc2, *wm1, *wm2, *wp1, *wp2, *wq, *wk;
    cudaGetSymbolAddress((void**)&xA, g_xA);
    cudaGetSymbolAddress((void**)&hidCA, g_hidCA);
    cudaGetSymbolAddress((void**)&hidMA, g_hidMA);
    cudaGetSymbolAddress((void**)&cgA, g_cgA);   cudaGetSymbolAddress((void**)&cA, g_cA);
    cudaGetSymbolAddress((void**)&memAg, g_memAg);
    cudaGetSymbolAddress((void**)&Q3, g_Q3);     cudaGetSymbolAddress((void**)&K3, g_K3);
    cudaGetSymbolAddress((void**)&oT3, g_oT3);   cudaGetSymbolAddress((void**)&cgT3, g_cgT3);
    cudaGetSymbolAddress((void**)&wc1, g_wc1);   cudaGetSymbolAddress((void**)&wc2, g_wc2);
    cudaGetSymbolAddress((void**)&wm1, g_wm1);   cudaGetSymbolAddress((void**)&wm2, g_wm2);
    cudaGetSymbolAddress((void**)&wp1, g_wp1);   cudaGetSymbolAddress((void**)&wp2, g_wp2);
    cudaGetSymbolAddress((void**)&wq, g_wq);     cudaGetSymbolAddress((void**)&wk, g_wk);

    dim3 wb(32, 8);
    wsplitT<<<dim3(HID_/32, C_/32),   wb>>>(c_w1, wc1, C_, HID_);   // top 768 rows only
    wsplitT<<<dim3(C_/32, HID_/32),   wb>>>(c_w2, wc2, HID_, C_);
    wsplitT<<<dim3(HID_/32, C_/32),   wb>>>(m_w1, wm1, C_, HID_);
    wsplitT<<<dim3(C_/32, HID_/32),   wb>>>(m_w2, wm2, HID_, C_);
    wsplitT<<<dim3(HID_/32, C_/32),   wb>>>(p_w1, wp1, C_, HID_);
    wsplitT<<<dim3(C_/32, HID_/32),   wb>>>(p_w2, wp2, HID_, C_);
    wsplitT<<<dim3(C_/32, C_/32),     wb>>>(q_w, wq, C_, C_);
    wsplitT<<<dim3(C_/32, C_/32),     wb>>>(k_w, wk, C_, C_);

    ln_kernel<<<B_*T_*N_, 256>>>(cur_fea, n1w, n1b, x, xA);
    initmem_kernel<<<(B_*MEM_*C_/2 + 255)/256, 256>>>(x, memA, memAg);

    float* mcur = memA;
    float* mnxt = memB;

    for (int t = 1; t < T_; t++) {
        // fork: mem/memAg ready on legacy stream
        cudaEventRecord(eA, 0);
        cudaStreamWaitEvent(sS, eA, 0);

        // ---- stream S: m-chain ----
        gemm_big(memAg, wm1, m_b1, nullptr, hidMA, ROWS_, HID_, C_, 1|4, sS);  // fc1_m
        gemm_sm (memAg, wk, k_b, kb, nullptr, ROWS_, C_, C_, 2, sS);           // k
        pack_qk<<<(64*196*192 + 255)/256, 256, 0, sS>>>(kb, K3, 1);
        cudaEventRecord(eK, sS);
        gemm_sm (hidMA, wm2, m_b2, memh, nullptr, ROWS_, C_, HID_, 2, sS);     // fc2_m

        // ---- legacy stream L: c-chain ----
        apw_fused<<<dim3(HID_/256, B_), 256>>>(mcur, c_w1, c_b1, bias2);
        const uint16_t* feaA = xA + (size_t)t * ROWS_ * 3 * C_;
        gemm_big(feaA, wc1, bias2, nullptr, hidCA, ROWS_, HID_, C_, 1|4|8, 0); // fc1_c
        gemm_sm (hidCA, wc2, c_b2, cg, cgA, ROWS_, C_, HID_, 2|4, 0);          // fc2_c
        cudaEventRecord(eCG, 0);
        cudaStreamWaitEvent(sS, eCG, 0);
        pack_cgT<<<dim3(3, 8, 64), wb, 0, sS>>>(cg, cgT3);                     // on S
        cudaEventRecord(eS2, sS);

        gemm_sm (cgA, wq, q_b, qb, nullptr, ROWS_, C_, C_, 2, 0);              // q
        pack_qk<<<(64*196*192 + 255)/256, 256>>>(qb, Q3, 0);
        cudaStreamWaitEvent(0, eK, 0);
        gemm_bat<<<dim3(2, 2, 64), 256, SMEM_BAT>>>(
            (const bf16*)Q3, (const bf16*)K3, o, nullptr, 196, 196, 384, 0);   // attn
        gate_kernel<<<(B_*H_*MEM_ + 255)/256, 256>>>(o, gate);
        pack_oT<<<dim3(7, 8, 64), wb>>>(o, oT3);
        cudaStreamWaitEvent(0, eS2, 0);                                        // cgT3 + memh ready
        gemm_bat<<<dim3(1, 2, 64), 256, SMEM_BAT>>>(
            (const bf16*)oT3, (const bf16*)cgT3, nullptr, cA, 196, 96, 768, 1); // cgather

        gemm_big(cA, wp1, p_b1, nullptr, hidCA, ROWS_, HID_, C_, 1|4, 0);      // fc1_p
        gemm_sm (hidCA, wp2, p_b2, c2, nullptr, ROWS_, C_, HID_, 2, 0);        // fc2_p

        float* dst = (t == T_ - 1) ? (float*)d_out : mnxt;
        final_kernel<<<B_*MEM_, 256>>>(c2, gate, memh, n2w, n2b, dst, memAg);

        float* tmp = mcur; mcur = mnxt; mnxt = tmp;
    }
}